// round 4
// baseline (speedup 1.0000x reference)
#include <cuda_runtime.h>
#include <math.h>

#define T_DIM 128
#define B_DIM 64
#define C_DIM 768
#define M_DIM (T_DIM * B_DIM)   // 8192
#define K_DW  31
#define EPSF  1e-5f

typedef unsigned long long ull;

// ---------------- scratch (static device allocations; no cudaMalloc) ----------------
__device__ float g_H  [M_DIM * C_DIM];       // layernorm out
__device__ float g_Y1 [M_DIM * C_DIM];       // pw1 + bn1
__device__ float g_S1 [M_DIM * C_DIM];       // lif1 spikes
__device__ float g_D  [M_DIM * C_DIM];       // depthwise out
__device__ float g_S2 [M_DIM * C_DIM];       // lif2 spikes
__device__ float g_Y2 [M_DIM * 2 * C_DIM];   // pw2 + bn3 (out | gate)
__device__ float g_Sg [M_DIM * C_DIM];       // lif(gate) spikes
__device__ float g_Y3 [M_DIM * C_DIM];       // gsu + gsu_bn
__device__ float g_Sg2[M_DIM * C_DIM];       // lif(gsu) spikes

// ---------------- packed f32x2 helpers (Blackwell FFMA2 path) ----------------
__device__ __forceinline__ ull dup2(float v) {
    ull r; asm("mov.b64 %0, {%1, %1};" : "=l"(r) : "f"(v)); return r;
}
__device__ __forceinline__ void fma2(ull &d, ull a, ull b) {
    asm("fma.rn.f32x2 %0, %1, %2, %0;" : "+l"(d) : "l"(a), "l"(b));
}
__device__ __forceinline__ float2 unpack2(ull v) {
    float2 r; asm("mov.b64 {%0, %1}, %2;" : "=f"(r.x), "=f"(r.y) : "l"(v)); return r;
}

// ---------------- block reduction helper ----------------
__inline__ __device__ float block_reduce_sum(float val, float* shmem) {
    int tid = threadIdx.x;
    #pragma unroll
    for (int o = 16; o > 0; o >>= 1) val += __shfl_xor_sync(0xffffffffu, val, o);
    if ((tid & 31) == 0) shmem[tid >> 5] = val;
    __syncthreads();
    float r = 0.0f;
    if (tid < 8) r = shmem[tid];
    if (tid < 32) {
        #pragma unroll
        for (int o = 4; o > 0; o >>= 1) r += __shfl_xor_sync(0xffffffffu, r, o);
    }
    if (tid == 0) shmem[0] = r;
    __syncthreads();
    r = shmem[0];
    __syncthreads();
    return r;
}

// ---------------- layernorm over C (one block per row) ----------------
__global__ void __launch_bounds__(256) ln_kernel(
    const float* __restrict__ x, const float* __restrict__ gam,
    const float* __restrict__ bet, float* __restrict__ out)
{
    __shared__ float red[32];
    int row = blockIdx.x;
    const float* xr = x + (size_t)row * C_DIM;
    float* orow = out + (size_t)row * C_DIM;
    int tid = threadIdx.x;

    float lx[3];
    float s = 0.0f;
    #pragma unroll
    for (int i = 0; i < 3; i++) { lx[i] = xr[tid + i * 256]; s += lx[i]; }
    float mean = block_reduce_sum(s, red) * (1.0f / C_DIM);

    float s2 = 0.0f;
    #pragma unroll
    for (int i = 0; i < 3; i++) { float d = lx[i] - mean; s2 += d * d; }
    float var = block_reduce_sum(s2, red) * (1.0f / C_DIM);
    float rstd = 1.0f / sqrtf(var + EPSF);

    #pragma unroll
    for (int i = 0; i < 3; i++) {
        int c = tid + i * 256;
        orow[c] = (lx[i] - mean) * rstd * gam[c] + bet[c];
    }
}

// ---------------- fp32 GEMM via packed FFMA2, 128x64 tile -----------------------
// Out[m,n] = bn( sum_k A[m,k]*W[n,k] + bias[n] )
// A: [M,K] row-major, W: [N,K] row-major. 128x64 tile, BK=16, 256 thr,
// 8m x 4n microtile (two 4-row m-quadrants). Small tiles -> many CTAs ->
// minimal wave-quantization tail; __launch_bounds__(256,2) pins >=2 CTA/SM.
#define BM 128
#define BN 64
#define BK 16
__global__ void __launch_bounds__(256, 2) gemm_bias_bn(
    const float* __restrict__ A, const float* __restrict__ W,
    const float* __restrict__ bias, const float* __restrict__ bnp,
    float* __restrict__ Out, int M, int N, int K)
{
    __shared__ float As[BK][BM + 4];
    __shared__ float Bs[BK][BN + 4];

    int tid = threadIdx.x;
    int bn0 = blockIdx.x * BN;
    int bm0 = blockIdx.y * BM;
    int tx = tid & 15;        // n direction: 4 floats each -> 64
    int ty = tid >> 4;        // m direction: 0..15, 4 rows per quadrant

    // global-load mapping
    int lrA = tid & 127;           // A row within tile
    int lkA = (tid >> 7) * 8;      // 0 or 8
    int lrB = tid & 63;            // B row within tile
    int lkB = (tid >> 6) * 4;      // 0,4,8,12
    const float* Ap = A + (size_t)(bm0 + lrA) * K + lkA;
    const float* Wp = W + (size_t)(bn0 + lrB) * K + lkB;

    ull acc[8][2];
    #pragma unroll
    for (int i = 0; i < 8; i++) { acc[i][0] = 0ull; acc[i][1] = 0ull; }

    // register prefetch for step 0
    float4 pa0 = *(const float4*)(Ap);
    float4 pa1 = *(const float4*)(Ap + 4);
    float4 pb  = *(const float4*)(Wp);

    for (int k0 = 0; k0 < K; k0 += BK) {
        __syncthreads();
        As[lkA + 0][lrA] = pa0.x; As[lkA + 1][lrA] = pa0.y;
        As[lkA + 2][lrA] = pa0.z; As[lkA + 3][lrA] = pa0.w;
        As[lkA + 4][lrA] = pa1.x; As[lkA + 5][lrA] = pa1.y;
        As[lkA + 6][lrA] = pa1.z; As[lkA + 7][lrA] = pa1.w;
        Bs[lkB + 0][lrB] = pb.x;  Bs[lkB + 1][lrB] = pb.y;
        Bs[lkB + 2][lrB] = pb.z;  Bs[lkB + 3][lrB] = pb.w;
        __syncthreads();

        if (k0 + BK < K) {
            pa0 = *(const float4*)(Ap + k0 + BK);
            pa1 = *(const float4*)(Ap + k0 + BK + 4);
            pb  = *(const float4*)(Wp + k0 + BK);
        }

        #pragma unroll
        for (int kk = 0; kk < BK; kk++) {
            float4 av0 = *(const float4*)&As[kk][ty * 4];
            float4 av1 = *(const float4*)&As[kk][ty * 4 + 64];
            ulonglong2 bq = *(const ulonglong2*)&Bs[kk][tx * 4];
            ull bp0 = bq.x, bp1 = bq.y;
            ull a;
            a = dup2(av0.x); fma2(acc[0][0], a, bp0); fma2(acc[0][1], a, bp1);
            a = dup2(av0.y); fma2(acc[1][0], a, bp0); fma2(acc[1][1], a, bp1);
            a = dup2(av0.z); fma2(acc[2][0], a, bp0); fma2(acc[2][1], a, bp1);
            a = dup2(av0.w); fma2(acc[3][0], a, bp0); fma2(acc[3][1], a, bp1);
            a = dup2(av1.x); fma2(acc[4][0], a, bp0); fma2(acc[4][1], a, bp1);
            a = dup2(av1.y); fma2(acc[5][0], a, bp0); fma2(acc[5][1], a, bp1);
            a = dup2(av1.z); fma2(acc[6][0], a, bp0); fma2(acc[6][1], a, bp1);
            a = dup2(av1.w); fma2(acc[7][0], a, bp0); fma2(acc[7][1], a, bp1);
        }
    }

    // epilogue: bias + (optional) BN affine, write float2 per n-pair
    #pragma unroll
    for (int jp = 0; jp < 2; jp++) {
        int n0 = bn0 + tx * 4 + jp * 2;
        float sc0 = 1.0f, sh0 = 0.0f, sc1 = 1.0f, sh1 = 0.0f;
        if (bnp) {
            float g0 = bnp[n0],     be0 = bnp[N + n0],     mm0 = bnp[2*N + n0],     vv0 = bnp[3*N + n0];
            float g1 = bnp[n0 + 1], be1 = bnp[N + n0 + 1], mm1 = bnp[2*N + n0 + 1], vv1 = bnp[3*N + n0 + 1];
            sc0 = g0 / sqrtf(vv0 + EPSF); sh0 = be0 - mm0 * sc0;
            sc1 = g1 / sqrtf(vv1 + EPSF); sh1 = be1 - mm1 * sc1;
        }
        float bs0 = bias[n0], bs1 = bias[n0 + 1];
        #pragma unroll
        for (int i = 0; i < 8; i++) {
            int m = bm0 + ty * 4 + ((i < 4) ? i : (64 + i - 4));
            float2 v = unpack2(acc[i][jp]);
            float2 o;
            o.x = (v.x + bs0) * sc0 + sh0;
            o.y = (v.y + bs1) * sc1 + sh1;
            *(float2*)&Out[(size_t)m * N + n0] = o;
        }
    }
}

// ---------------- LIF scan (optionally fused BN affine and elementwise multiply) --
__global__ void __launch_bounds__(256) lif_kernel(
    const float* __restrict__ X, int ldx,
    const float* __restrict__ Mul, int ldm,
    const float* __restrict__ bnp,
    float* __restrict__ S)
{
    int j = blockIdx.x * blockDim.x + threadIdx.x;
    if (j >= B_DIM * C_DIM) return;
    int b = j / C_DIM, c = j % C_DIM;

    float sc = 1.0f, sh = 0.0f;
    if (bnp) {
        float g = bnp[c], be = bnp[C_DIM + c], mm = bnp[2 * C_DIM + c], vv = bnp[3 * C_DIM + c];
        sc = g / sqrtf(vv + EPSF);
        sh = be - mm * sc;
    }

    const float* xp = X + (size_t)b * ldx + c;
    const float* mp = Mul ? (Mul + (size_t)b * ldm + c) : nullptr;
    float* sp = S + (size_t)j;
    size_t stx = (size_t)B_DIM * ldx;
    size_t stm = (size_t)B_DIM * ldm;
    size_t sts = (size_t)B_DIM * C_DIM;

    float vm = 0.0f;
    for (int t = 0; t < T_DIM; t++) {
        float xv = xp[(size_t)t * stx];
        if (mp) xv *= mp[(size_t)t * stm];
        xv = xv * sc + sh;
        vm = vm * 0.5f + xv;
        float s = (vm >= 1.0f) ? 1.0f : 0.0f;
        vm = (s > 0.0f) ? 0.0f : vm;
        sp[(size_t)t * sts] = s;
    }
}

// ---------------- depthwise conv over time (K=31, SAME zero pad) ----------------
__global__ void __launch_bounds__(256) dw_kernel(
    const float* __restrict__ S1, const float* __restrict__ w,
    const float* __restrict__ bvec, float* __restrict__ Dout)
{
    __shared__ float sx[T_DIM][64];
    int b  = blockIdx.x;
    int c0 = blockIdx.y * 64;
    int tid = threadIdx.x;

    for (int i = tid; i < T_DIM * 64; i += 256) {
        int t = i >> 6, ci = i & 63;
        sx[t][ci] = S1[((size_t)t * B_DIM + b) * C_DIM + c0 + ci];
    }
    __syncthreads();

    int ci = tid & 63;
    int tg = tid >> 6;
    int c  = c0 + ci;

    float wr[K_DW];
    #pragma unroll
    for (int k = 0; k < K_DW; k++) wr[k] = w[c * K_DW + k];
    float bb = bvec[c];

    for (int t = tg * 32; t < tg * 32 + 32; t++) {
        float acc = bb;
        #pragma unroll
        for (int k = 0; k < K_DW; k++) {
            int tt = t + k - 15;
            if (tt >= 0 && tt < T_DIM) acc += sx[tt][ci] * wr[k];
        }
        Dout[((size_t)t * B_DIM + b) * C_DIM + c] = acc;
    }
}

// ---------------- launch ----------------
extern "C" void kernel_launch(void* const* d_in, const int* in_sizes, int n_in,
                              void* d_out, int out_size)
{
    const float* x        = (const float*)d_in[0];
    const float* ln_g     = (const float*)d_in[1];
    const float* ln_b     = (const float*)d_in[2];
    const float* pw1_w    = (const float*)d_in[3];
    const float* pw1_b    = (const float*)d_in[4];
    const float* bn1_p    = (const float*)d_in[5];
    const float* dw_w     = (const float*)d_in[6];
    const float* dw_b     = (const float*)d_in[7];
    const float* bn2_p    = (const float*)d_in[8];
    const float* pw2_w    = (const float*)d_in[9];
    const float* pw2_b    = (const float*)d_in[10];
    const float* bn3_p    = (const float*)d_in[11];
    const float* gsu_w    = (const float*)d_in[12];
    const float* gsu_b    = (const float*)d_in[13];
    const float* gsu_bn_p = (const float*)d_in[14];

    float *H, *Y1, *S1, *D, *S2, *Y2, *Sg, *Y3, *Sg2;
    cudaGetSymbolAddress((void**)&H,   g_H);
    cudaGetSymbolAddress((void**)&Y1,  g_Y1);
    cudaGetSymbolAddress((void**)&S1,  g_S1);
    cudaGetSymbolAddress((void**)&D,   g_D);
    cudaGetSymbolAddress((void**)&S2,  g_S2);
    cudaGetSymbolAddress((void**)&Y2,  g_Y2);
    cudaGetSymbolAddress((void**)&Sg,  g_Sg);
    cudaGetSymbolAddress((void**)&Y3,  g_Y3);
    cudaGetSymbolAddress((void**)&Sg2, g_Sg2);

    const int lif_blocks = (B_DIM * C_DIM + 255) / 256;   // 192

    // 1) LayerNorm
    ln_kernel<<<M_DIM, 256>>>(x, ln_g, ln_b, H);

    // 2) pw1 + bias + bn1
    gemm_bias_bn<<<dim3(C_DIM / BN, M_DIM / BM), 256>>>(
        H, pw1_w, pw1_b, bn1_p, Y1, M_DIM, C_DIM, C_DIM);

    // 3) LIF -> S1
    lif_kernel<<<lif_blocks, 256>>>(Y1, C_DIM, nullptr, 0, nullptr, S1);

    // 4) depthwise over time
    dw_kernel<<<dim3(B_DIM, C_DIM / 64), 256>>>(S1, dw_w, dw_b, D);

    // 5) BN2 + LIF -> S2
    lif_kernel<<<lif_blocks, 256>>>(D, C_DIM, nullptr, 0, bn2_p, S2);

    // 6) pw2 + bias + bn3 -> [out | gate]
    gemm_bias_bn<<<dim3(2 * C_DIM / BN, M_DIM / BM), 256>>>(
        S2, pw2_w, pw2_b, bn3_p, Y2, M_DIM, 2 * C_DIM, C_DIM);

    // 7) LIF(gate half) -> Sg
    lif_kernel<<<lif_blocks, 256>>>(Y2 + C_DIM, 2 * C_DIM, nullptr, 0, nullptr, Sg);

    // 8) gsu GEMM + bias + gsu_bn
    gemm_bias_bn<<<dim3(C_DIM / BN, M_DIM / BM), 256>>>(
        Sg, gsu_w, gsu_b, gsu_bn_p, Y3, M_DIM, C_DIM, C_DIM);

    // 9) LIF -> Sg2
    lif_kernel<<<lif_blocks, 256>>>(Y3, C_DIM, nullptr, 0, nullptr, Sg2);

    // 10) final LIF on out*Sg2 -> d_out
    lif_kernel<<<lif_blocks, 256>>>(Y2, 2 * C_DIM, Sg2, C_DIM, nullptr, (float*)d_out);
}

// round 5
// speedup vs baseline: 1.2946x; 1.2946x over previous
#include <cuda_runtime.h>
#include <math.h>

#define T_DIM 128
#define B_DIM 64
#define C_DIM 768
#define M_DIM (T_DIM * B_DIM)   // 8192
#define K_DW  31
#define EPSF  1e-5f

typedef unsigned long long ull;

// ---------------- scratch (static device allocations; no cudaMalloc) ----------------
__device__ float g_H  [M_DIM * C_DIM];       // layernorm out
__device__ float g_Y1 [M_DIM * C_DIM];       // pw1 + bn1
__device__ float g_S1 [M_DIM * C_DIM];       // lif1 spikes
__device__ float g_D  [M_DIM * C_DIM];       // depthwise out
__device__ float g_S2 [M_DIM * C_DIM];       // lif2 spikes
__device__ float g_Y2 [M_DIM * 2 * C_DIM];   // pw2 + bn3 (out | gate)
__device__ float g_Sg [M_DIM * C_DIM];       // lif(gate) spikes
__device__ float g_Y3 [M_DIM * C_DIM];       // gsu + gsu_bn
__device__ float g_Sg2[M_DIM * C_DIM];       // lif(gsu) spikes

// ---------------- packed f32x2 helpers (Blackwell FFMA2 path) ----------------
__device__ __forceinline__ ull dup2(float v) {
    ull r; asm("mov.b64 %0, {%1, %1};" : "=l"(r) : "f"(v)); return r;
}
__device__ __forceinline__ ull pack2(float lo, float hi) {
    ull r; asm("mov.b64 %0, {%1, %2};" : "=l"(r) : "f"(lo), "f"(hi)); return r;
}
__device__ __forceinline__ void fma2(ull &d, ull a, ull b) {
    asm("fma.rn.f32x2 %0, %1, %2, %0;" : "+l"(d) : "l"(a), "l"(b));
}
__device__ __forceinline__ float2 unpack2(ull v) {
    float2 r; asm("mov.b64 {%0, %1}, %2;" : "=f"(r.x), "=f"(r.y) : "l"(v)); return r;
}

// ---------------- block reduction helper ----------------
__inline__ __device__ float block_reduce_sum(float val, float* shmem) {
    int tid = threadIdx.x;
    #pragma unroll
    for (int o = 16; o > 0; o >>= 1) val += __shfl_xor_sync(0xffffffffu, val, o);
    if ((tid & 31) == 0) shmem[tid >> 5] = val;
    __syncthreads();
    float r = 0.0f;
    if (tid < 8) r = shmem[tid];
    if (tid < 32) {
        #pragma unroll
        for (int o = 4; o > 0; o >>= 1) r += __shfl_xor_sync(0xffffffffu, r, o);
    }
    if (tid == 0) shmem[0] = r;
    __syncthreads();
    r = shmem[0];
    __syncthreads();
    return r;
}

// ---------------- layernorm over C (one block per row) ----------------
__global__ void __launch_bounds__(256) ln_kernel(
    const float* __restrict__ x, const float* __restrict__ gam,
    const float* __restrict__ bet, float* __restrict__ out)
{
    __shared__ float red[32];
    int row = blockIdx.x;
    const float* xr = x + (size_t)row * C_DIM;
    float* orow = out + (size_t)row * C_DIM;
    int tid = threadIdx.x;

    float lx[3];
    float s = 0.0f;
    #pragma unroll
    for (int i = 0; i < 3; i++) { lx[i] = xr[tid + i * 256]; s += lx[i]; }
    float mean = block_reduce_sum(s, red) * (1.0f / C_DIM);

    float s2 = 0.0f;
    #pragma unroll
    for (int i = 0; i < 3; i++) { float d = lx[i] - mean; s2 += d * d; }
    float var = block_reduce_sum(s2, red) * (1.0f / C_DIM);
    float rstd = 1.0f / sqrtf(var + EPSF);

    #pragma unroll
    for (int i = 0; i < 3; i++) {
        int c = tid + i * 256;
        orow[c] = (lx[i] - mean) * rstd * gam[c] + bet[c];
    }
}

// ---------------- fp32 GEMM via packed FFMA2 (R2 config, reuse-friendly order) ----
// Out[m,n] = bn( sum_k A[m,k]*W[n,k] + bias[n] )
// A: [M,K] row-major, W: [N,K] row-major. 128x128 tile, BK=16, 256 thr,
// 8x8 microtile split as two 4x4 quadrants (m: ty*4 / +64, n: tx*4 / +64).
#define BM 128
#define BN 128
#define BK 16
__global__ void __launch_bounds__(256) gemm_bias_bn(
    const float* __restrict__ A, const float* __restrict__ W,
    const float* __restrict__ bias, const float* __restrict__ bnp,
    float* __restrict__ Out, int M, int N, int K)
{
    __shared__ float As[BK][BM + 4];
    __shared__ float Bs[BK][BN + 4];

    int tid = threadIdx.x;
    int bn0 = blockIdx.x * BN;
    int bm0 = blockIdx.y * BM;
    int tx = tid & 15;        // n direction
    int ty = tid >> 4;        // m direction

    // global-load mapping: 256 threads cover 128 rows x 2 k-halves
    int lr = tid & 127;            // row within tile
    int lk = (tid >> 7) * 8;       // 0 or 8
    const float* Ap = A + (size_t)(bm0 + lr) * K + lk;
    const float* Wp = W + (size_t)(bn0 + lr) * K + lk;

    ull acc[8][4];
    #pragma unroll
    for (int i = 0; i < 8; i++)
        #pragma unroll
        for (int j = 0; j < 4; j++) acc[i][j] = 0ull;

    // register prefetch for step 0
    float4 pa0 = *(const float4*)(Ap);
    float4 pa1 = *(const float4*)(Ap + 4);
    float4 pb0 = *(const float4*)(Wp);
    float4 pb1 = *(const float4*)(Wp + 4);

    for (int k0 = 0; k0 < K; k0 += BK) {
        __syncthreads();
        As[lk + 0][lr] = pa0.x; As[lk + 1][lr] = pa0.y;
        As[lk + 2][lr] = pa0.z; As[lk + 3][lr] = pa0.w;
        As[lk + 4][lr] = pa1.x; As[lk + 5][lr] = pa1.y;
        As[lk + 6][lr] = pa1.z; As[lk + 7][lr] = pa1.w;
        Bs[lk + 0][lr] = pb0.x; Bs[lk + 1][lr] = pb0.y;
        Bs[lk + 2][lr] = pb0.z; Bs[lk + 3][lr] = pb0.w;
        Bs[lk + 4][lr] = pb1.x; Bs[lk + 5][lr] = pb1.y;
        Bs[lk + 6][lr] = pb1.z; Bs[lk + 7][lr] = pb1.w;
        __syncthreads();

        if (k0 + BK < K) {
            pa0 = *(const float4*)(Ap + k0 + BK);
            pa1 = *(const float4*)(Ap + k0 + BK + 4);
            pb0 = *(const float4*)(Wp + k0 + BK);
            pb1 = *(const float4*)(Wp + k0 + BK + 4);
        }

        #pragma unroll
        for (int kk = 0; kk < BK; kk++) {
            float4 av0 = *(const float4*)&As[kk][ty * 4];
            float4 av1 = *(const float4*)&As[kk][ty * 4 + 64];
            float4 bv0 = *(const float4*)&Bs[kk][tx * 4];
            float4 bv1 = *(const float4*)&Bs[kk][tx * 4 + 64];
            ull bp0 = pack2(bv0.x, bv0.y);
            ull bp1 = pack2(bv0.z, bv0.w);
            ull bp2 = pack2(bv1.x, bv1.y);
            ull bp3 = pack2(bv1.z, bv1.w);

            // 2D-blocked order: repeats in BOTH operand slots inside a short
            // window (b held for 4 consecutive, a-window of 4 live dups) so
            // the operand-reuse caches can skip RF bank reads.
            ull A0 = dup2(av0.x), A1 = dup2(av0.y), A2 = dup2(av0.z), A3 = dup2(av0.w);
            fma2(acc[0][0], A0, bp0); fma2(acc[1][0], A1, bp0); fma2(acc[2][0], A2, bp0); fma2(acc[3][0], A3, bp0);
            fma2(acc[0][1], A0, bp1); fma2(acc[1][1], A1, bp1); fma2(acc[2][1], A2, bp1); fma2(acc[3][1], A3, bp1);
            fma2(acc[0][2], A0, bp2); fma2(acc[1][2], A1, bp2); fma2(acc[2][2], A2, bp2); fma2(acc[3][2], A3, bp2);
            fma2(acc[0][3], A0, bp3); fma2(acc[1][3], A1, bp3); fma2(acc[2][3], A2, bp3); fma2(acc[3][3], A3, bp3);
            ull A4 = dup2(av1.x), A5 = dup2(av1.y), A6 = dup2(av1.z), A7 = dup2(av1.w);
            fma2(acc[4][0], A4, bp0); fma2(acc[5][0], A5, bp0); fma2(acc[6][0], A6, bp0); fma2(acc[7][0], A7, bp0);
            fma2(acc[4][1], A4, bp1); fma2(acc[5][1], A5, bp1); fma2(acc[6][1], A6, bp1); fma2(acc[7][1], A7, bp1);
            fma2(acc[4][2], A4, bp2); fma2(acc[5][2], A5, bp2); fma2(acc[6][2], A6, bp2); fma2(acc[7][2], A7, bp2);
            fma2(acc[4][3], A4, bp3); fma2(acc[5][3], A5, bp3); fma2(acc[6][3], A6, bp3); fma2(acc[7][3], A7, bp3);
        }
    }

    // epilogue: bias + (optional) BN affine, write float2 per n-pair
    #pragma unroll
    for (int half = 0; half < 2; half++) {
        #pragma unroll
        for (int jp = 0; jp < 2; jp++) {
            int n0 = bn0 + tx * 4 + half * 64 + jp * 2;
            float sc0 = 1.0f, sh0 = 0.0f, sc1 = 1.0f, sh1 = 0.0f;
            if (bnp) {
                float g0 = bnp[n0],     be0 = bnp[N + n0],     mm0 = bnp[2*N + n0],     vv0 = bnp[3*N + n0];
                float g1 = bnp[n0 + 1], be1 = bnp[N + n0 + 1], mm1 = bnp[2*N + n0 + 1], vv1 = bnp[3*N + n0 + 1];
                sc0 = g0 / sqrtf(vv0 + EPSF); sh0 = be0 - mm0 * sc0;
                sc1 = g1 / sqrtf(vv1 + EPSF); sh1 = be1 - mm1 * sc1;
            }
            float bs0 = bias[n0], bs1 = bias[n0 + 1];
            #pragma unroll
            for (int i = 0; i < 8; i++) {
                int m = bm0 + ty * 4 + ((i < 4) ? i : (64 + i - 4));
                float2 v = unpack2(acc[i][half * 2 + jp]);
                float2 o;
                o.x = (v.x + bs0) * sc0 + sh0;
                o.y = (v.y + bs1) * sc1 + sh1;
                *(float2*)&Out[(size_t)m * N + n0] = o;
            }
        }
    }
}

// ---------------- LIF scan (optionally fused BN affine and elementwise multiply) --
__global__ void __launch_bounds__(256) lif_kernel(
    const float* __restrict__ X, int ldx,
    const float* __restrict__ Mul, int ldm,
    const float* __restrict__ bnp,
    float* __restrict__ S)
{
    int j = blockIdx.x * blockDim.x + threadIdx.x;
    if (j >= B_DIM * C_DIM) return;
    int b = j / C_DIM, c = j % C_DIM;

    float sc = 1.0f, sh = 0.0f;
    if (bnp) {
        float g = bnp[c], be = bnp[C_DIM + c], mm = bnp[2 * C_DIM + c], vv = bnp[3 * C_DIM + c];
        sc = g / sqrtf(vv + EPSF);
        sh = be - mm * sc;
    }

    const float* xp = X + (size_t)b * ldx + c;
    const float* mp = Mul ? (Mul + (size_t)b * ldm + c) : nullptr;
    float* sp = S + (size_t)j;
    size_t stx = (size_t)B_DIM * ldx;
    size_t stm = (size_t)B_DIM * ldm;
    size_t sts = (size_t)B_DIM * C_DIM;

    float vm = 0.0f;
    #pragma unroll 4
    for (int t = 0; t < T_DIM; t++) {
        float xv = xp[(size_t)t * stx];
        if (mp) xv *= mp[(size_t)t * stm];
        xv = xv * sc + sh;
        vm = vm * 0.5f + xv;
        float s = (vm >= 1.0f) ? 1.0f : 0.0f;
        vm = (s > 0.0f) ? 0.0f : vm;
        sp[(size_t)t * sts] = s;
    }
}

// ---------------- depthwise conv over time (K=31, SAME zero pad) ----------------
// Padded smem (15 zeros each side) + scatter-form register blocking:
// each thread owns 32 consecutive t outputs; 62 LDS feed 992 FMAs.
#define DW_PAD 15
__global__ void __launch_bounds__(256) dw_kernel(
    const float* __restrict__ S1, const float* __restrict__ w,
    const float* __restrict__ bvec, float* __restrict__ Dout)
{
    __shared__ float sx[T_DIM + 2 * DW_PAD][64];   // 158 x 64
    int b  = blockIdx.x;
    int c0 = blockIdx.y * 64;
    int tid = threadIdx.x;

    // zero the pads
    for (int i = tid; i < 2 * DW_PAD * 64; i += 256) {
        int r = i >> 6, ci = i & 63;
        if (r < DW_PAD) sx[r][ci] = 0.0f;
        else            sx[T_DIM + DW_PAD + (r - DW_PAD)][ci] = 0.0f;
    }
    // load center
    for (int i = tid; i < T_DIM * 64; i += 256) {
        int t = i >> 6, ci = i & 63;
        sx[t + DW_PAD][ci] = S1[((size_t)t * B_DIM + b) * C_DIM + c0 + ci];
    }
    __syncthreads();

    int ci = tid & 63;
    int tg = tid >> 6;      // 4 groups of 32 consecutive t
    int c  = c0 + ci;
    int t0 = tg * 32;

    float wr[K_DW];
    #pragma unroll
    for (int k = 0; k < K_DW; k++) wr[k] = w[c * K_DW + k];
    float bb = bvec[c];

    float acc[32];
    #pragma unroll
    for (int i = 0; i < 32; i++) acc[i] = bb;

    #pragma unroll
    for (int dt = -DW_PAD; dt <= 31 + DW_PAD; dt++) {       // 62 loads
        float sv = sx[t0 + dt + DW_PAD][ci];
        #pragma unroll
        for (int i = 0; i < 32; i++) {
            int k = dt - i + DW_PAD;                        // compile-time per (dt,i)
            if (k >= 0 && k < K_DW) acc[i] += sv * wr[k];
        }
    }

    #pragma unroll
    for (int i = 0; i < 32; i++) {
        int t = t0 + i;
        Dout[((size_t)t * B_DIM + b) * C_DIM + c] = acc[i];
    }
}

// ---------------- launch ----------------
extern "C" void kernel_launch(void* const* d_in, const int* in_sizes, int n_in,
                              void* d_out, int out_size)
{
    const float* x        = (const float*)d_in[0];
    const float* ln_g     = (const float*)d_in[1];
    const float* ln_b     = (const float*)d_in[2];
    const float* pw1_w    = (const float*)d_in[3];
    const float* pw1_b    = (const float*)d_in[4];
    const float* bn1_p    = (const float*)d_in[5];
    const float* dw_w     = (const float*)d_in[6];
    const float* dw_b     = (const float*)d_in[7];
    const float* bn2_p    = (const float*)d_in[8];
    const float* pw2_w    = (const float*)d_in[9];
    const float* pw2_b    = (const float*)d_in[10];
    const float* bn3_p    = (const float*)d_in[11];
    const float* gsu_w    = (const float*)d_in[12];
    const float* gsu_b    = (const float*)d_in[13];
    const float* gsu_bn_p = (const float*)d_in[14];

    float *H, *Y1, *S1, *D, *S2, *Y2, *Sg, *Y3, *Sg2;
    cudaGetSymbolAddress((void**)&H,   g_H);
    cudaGetSymbolAddress((void**)&Y1,  g_Y1);
    cudaGetSymbolAddress((void**)&S1,  g_S1);
    cudaGetSymbolAddress((void**)&D,   g_D);
    cudaGetSymbolAddress((void**)&S2,  g_S2);
    cudaGetSymbolAddress((void**)&Y2,  g_Y2);
    cudaGetSymbolAddress((void**)&Sg,  g_Sg);
    cudaGetSymbolAddress((void**)&Y3,  g_Y3);
    cudaGetSymbolAddress((void**)&Sg2, g_Sg2);

    const int lif_blocks = (B_DIM * C_DIM + 255) / 256;   // 192

    // 1) LayerNorm
    ln_kernel<<<M_DIM, 256>>>(x, ln_g, ln_b, H);

    // 2) pw1 + bias + bn1
    gemm_bias_bn<<<dim3(C_DIM / BN, M_DIM / BM), 256>>>(
        H, pw1_w, pw1_b, bn1_p, Y1, M_DIM, C_DIM, C_DIM);

    // 3) LIF -> S1
    lif_kernel<<<lif_blocks, 256>>>(Y1, C_DIM, nullptr, 0, nullptr, S1);

    // 4) depthwise over time
    dw_kernel<<<dim3(B_DIM, C_DIM / 64), 256>>>(S1, dw_w, dw_b, D);

    // 5) BN2 + LIF -> S2
    lif_kernel<<<lif_blocks, 256>>>(D, C_DIM, nullptr, 0, bn2_p, S2);

    // 6) pw2 + bias + bn3 -> [out | gate]
    gemm_bias_bn<<<dim3(2 * C_DIM / BN, M_DIM / BM), 256>>>(
        S2, pw2_w, pw2_b, bn3_p, Y2, M_DIM, 2 * C_DIM, C_DIM);

    // 7) LIF(gate half) -> Sg
    lif_kernel<<<lif_blocks, 256>>>(Y2 + C_DIM, 2 * C_DIM, nullptr, 0, nullptr, Sg);

    // 8) gsu GEMM + bias + gsu_bn
    gemm_bias_bn<<<dim3(C_DIM / BN, M_DIM / BM), 256>>>(
        Sg, gsu_w, gsu_b, gsu_bn_p, Y3, M_DIM, C_DIM, C_DIM);

    // 9) LIF -> Sg2
    lif_kernel<<<lif_blocks, 256>>>(Y3, C_DIM, nullptr, 0, nullptr, Sg2);

    // 10) final LIF on out*Sg2 -> d_out
    lif_kernel<<<lif_blocks, 256>>>(Y2, 2 * C_DIM, Sg2, C_DIM, nullptr, (float*)d_out);
}

// round 6
// speedup vs baseline: 1.8353x; 1.4177x over previous
#include <cuda_runtime.h>
#include <cuda_bf16.h>
#include <math.h>

#define T_DIM 128
#define B_DIM 64
#define C_DIM 768
#define M_DIM (T_DIM * B_DIM)   // 8192
#define K_DW  31
#define EPSF  1e-5f

typedef unsigned long long ull;
typedef unsigned int uint32;

// ---------------- scratch (static device allocations; no cudaMalloc) ----------------
__device__ float g_H  [M_DIM * C_DIM];       // layernorm out
__device__ float g_Y1 [M_DIM * C_DIM];       // pw1 + bn1
__device__ float g_S1 [M_DIM * C_DIM];       // lif1 spikes (fp32, feeds dw)
__device__ float g_D  [M_DIM * C_DIM];       // depthwise out
__device__ float g_Y2 [M_DIM * 2 * C_DIM];   // pw2 + bn3 (out | gate)
__device__ float g_Y3 [M_DIM * C_DIM];       // gsu + gsu_bn
__device__ float g_Sg2[M_DIM * C_DIM];       // lif(gsu) spikes (fp32, final mul)
__device__ __nv_bfloat16 g_S2b[M_DIM * C_DIM];   // lif2 spikes (bf16, feeds gemm2)
__device__ __nv_bfloat16 g_Sgb[M_DIM * C_DIM];   // lif(gate) spikes (bf16, feeds gemm3)
// weight splits (bf16 x3)
__device__ __nv_bfloat16 g_W2hi[2 * C_DIM * C_DIM];
__device__ __nv_bfloat16 g_W2mi[2 * C_DIM * C_DIM];
__device__ __nv_bfloat16 g_W2lo[2 * C_DIM * C_DIM];
__device__ __nv_bfloat16 g_Wghi[C_DIM * C_DIM];
__device__ __nv_bfloat16 g_Wgmi[C_DIM * C_DIM];
__device__ __nv_bfloat16 g_Wglo[C_DIM * C_DIM];

// ---------------- packed f32x2 helpers ----------------
__device__ __forceinline__ ull dup2(float v) {
    ull r; asm("mov.b64 %0, {%1, %1};" : "=l"(r) : "f"(v)); return r;
}
__device__ __forceinline__ ull pack2(float lo, float hi) {
    ull r; asm("mov.b64 %0, {%1, %2};" : "=l"(r) : "f"(lo), "f"(hi)); return r;
}
__device__ __forceinline__ void fma2(ull &d, ull a, ull b) {
    asm("fma.rn.f32x2 %0, %1, %2, %0;" : "+l"(d) : "l"(a), "l"(b));
}
__device__ __forceinline__ float2 unpack2(ull v) {
    float2 r; asm("mov.b64 {%0, %1}, %2;" : "=f"(r.x), "=f"(r.y) : "l"(v)); return r;
}

// ---------------- bf16 mma m16n8k16 ----------------
__device__ __forceinline__ void mma_bf16(float* c, const uint32* a, uint32 b0, uint32 b1) {
    asm volatile(
        "mma.sync.aligned.m16n8k16.row.col.f32.bf16.bf16.f32 "
        "{%0,%1,%2,%3}, {%4,%5,%6,%7}, {%8,%9}, {%0,%1,%2,%3};"
        : "+f"(c[0]), "+f"(c[1]), "+f"(c[2]), "+f"(c[3])
        : "r"(a[0]), "r"(a[1]), "r"(a[2]), "r"(a[3]), "r"(b0), "r"(b1));
}

// ---------------- weight split: w = hi + mid + lo (bf16 each) ----------------
__global__ void __launch_bounds__(256) split_w_kernel(
    const float* __restrict__ W,
    __nv_bfloat16* __restrict__ hi, __nv_bfloat16* __restrict__ mi,
    __nv_bfloat16* __restrict__ lo, int n)
{
    int i = blockIdx.x * blockDim.x + threadIdx.x;
    if (i >= n) return;
    float w = W[i];
    __nv_bfloat16 h = __float2bfloat16(w);
    float r1 = w - __bfloat162float(h);
    __nv_bfloat16 m = __float2bfloat16(r1);
    float r2 = r1 - __bfloat162float(m);
    hi[i] = h; mi[i] = m; lo[i] = __float2bfloat16(r2);
}

// ---------------- block reduction helper ----------------
__inline__ __device__ float block_reduce_sum(float val, float* shmem) {
    int tid = threadIdx.x;
    #pragma unroll
    for (int o = 16; o > 0; o >>= 1) val += __shfl_xor_sync(0xffffffffu, val, o);
    if ((tid & 31) == 0) shmem[tid >> 5] = val;
    __syncthreads();
    float r = 0.0f;
    if (tid < 8) r = shmem[tid];
    if (tid < 32) {
        #pragma unroll
        for (int o = 4; o > 0; o >>= 1) r += __shfl_xor_sync(0xffffffffu, r, o);
    }
    if (tid == 0) shmem[0] = r;
    __syncthreads();
    r = shmem[0];
    __syncthreads();
    return r;
}

// ---------------- layernorm over C (one block per row) ----------------
__global__ void __launch_bounds__(256) ln_kernel(
    const float* __restrict__ x, const float* __restrict__ gam,
    const float* __restrict__ bet, float* __restrict__ out)
{
    __shared__ float red[32];
    int row = blockIdx.x;
    const float* xr = x + (size_t)row * C_DIM;
    float* orow = out + (size_t)row * C_DIM;
    int tid = threadIdx.x;

    float lx[3];
    float s = 0.0f;
    #pragma unroll
    for (int i = 0; i < 3; i++) { lx[i] = xr[tid + i * 256]; s += lx[i]; }
    float mean = block_reduce_sum(s, red) * (1.0f / C_DIM);

    float s2 = 0.0f;
    #pragma unroll
    for (int i = 0; i < 3; i++) { float d = lx[i] - mean; s2 += d * d; }
    float var = block_reduce_sum(s2, red) * (1.0f / C_DIM);
    float rstd = 1.0f / sqrtf(var + EPSF);

    #pragma unroll
    for (int i = 0; i < 3; i++) {
        int c = tid + i * 256;
        orow[c] = (lx[i] - mean) * rstd * gam[c] + bet[c];
    }
}

// ---------------- fp32 GEMM via packed FFMA2 (GEMM1 only) ----------------
#define BM 128
#define BN 128
#define BK 16
__global__ void __launch_bounds__(256) gemm_bias_bn(
    const float* __restrict__ A, const float* __restrict__ W,
    const float* __restrict__ bias, const float* __restrict__ bnp,
    float* __restrict__ Out, int M, int N, int K)
{
    __shared__ float As[BK][BM + 4];
    __shared__ float Bs[BK][BN + 4];

    int tid = threadIdx.x;
    int bn0 = blockIdx.x * BN;
    int bm0 = blockIdx.y * BM;
    int tx = tid & 15;
    int ty = tid >> 4;

    int lr = tid & 127;
    int lk = (tid >> 7) * 8;
    const float* Ap = A + (size_t)(bm0 + lr) * K + lk;
    const float* Wp = W + (size_t)(bn0 + lr) * K + lk;

    ull acc[8][4];
    #pragma unroll
    for (int i = 0; i < 8; i++)
        #pragma unroll
        for (int j = 0; j < 4; j++) acc[i][j] = 0ull;

    float4 pa0 = *(const float4*)(Ap);
    float4 pa1 = *(const float4*)(Ap + 4);
    float4 pb0 = *(const float4*)(Wp);
    float4 pb1 = *(const float4*)(Wp + 4);

    for (int k0 = 0; k0 < K; k0 += BK) {
        __syncthreads();
        As[lk + 0][lr] = pa0.x; As[lk + 1][lr] = pa0.y;
        As[lk + 2][lr] = pa0.z; As[lk + 3][lr] = pa0.w;
        As[lk + 4][lr] = pa1.x; As[lk + 5][lr] = pa1.y;
        As[lk + 6][lr] = pa1.z; As[lk + 7][lr] = pa1.w;
        Bs[lk + 0][lr] = pb0.x; Bs[lk + 1][lr] = pb0.y;
        Bs[lk + 2][lr] = pb0.z; Bs[lk + 3][lr] = pb0.w;
        Bs[lk + 4][lr] = pb1.x; Bs[lk + 5][lr] = pb1.y;
        Bs[lk + 6][lr] = pb1.z; Bs[lk + 7][lr] = pb1.w;
        __syncthreads();

        if (k0 + BK < K) {
            pa0 = *(const float4*)(Ap + k0 + BK);
            pa1 = *(const float4*)(Ap + k0 + BK + 4);
            pb0 = *(const float4*)(Wp + k0 + BK);
            pb1 = *(const float4*)(Wp + k0 + BK + 4);
        }

        #pragma unroll
        for (int kk = 0; kk < BK; kk++) {
            float4 av0 = *(const float4*)&As[kk][ty * 4];
            float4 av1 = *(const float4*)&As[kk][ty * 4 + 64];
            float4 bv0 = *(const float4*)&Bs[kk][tx * 4];
            float4 bv1 = *(const float4*)&Bs[kk][tx * 4 + 64];
            ull bp0 = pack2(bv0.x, bv0.y);
            ull bp1 = pack2(bv0.z, bv0.w);
            ull bp2 = pack2(bv1.x, bv1.y);
            ull bp3 = pack2(bv1.z, bv1.w);
            ull A0 = dup2(av0.x), A1 = dup2(av0.y), A2 = dup2(av0.z), A3 = dup2(av0.w);
            fma2(acc[0][0], A0, bp0); fma2(acc[1][0], A1, bp0); fma2(acc[2][0], A2, bp0); fma2(acc[3][0], A3, bp0);
            fma2(acc[0][1], A0, bp1); fma2(acc[1][1], A1, bp1); fma2(acc[2][1], A2, bp1); fma2(acc[3][1], A3, bp1);
            fma2(acc[0][2], A0, bp2); fma2(acc[1][2], A1, bp2); fma2(acc[2][2], A2, bp2); fma2(acc[3][2], A3, bp2);
            fma2(acc[0][3], A0, bp3); fma2(acc[1][3], A1, bp3); fma2(acc[2][3], A2, bp3); fma2(acc[3][3], A3, bp3);
            ull A4 = dup2(av1.x), A5 = dup2(av1.y), A6 = dup2(av1.z), A7 = dup2(av1.w);
            fma2(acc[4][0], A4, bp0); fma2(acc[5][0], A5, bp0); fma2(acc[6][0], A6, bp0); fma2(acc[7][0], A7, bp0);
            fma2(acc[4][1], A4, bp1); fma2(acc[5][1], A5, bp1); fma2(acc[6][1], A6, bp1); fma2(acc[7][1], A7, bp1);
            fma2(acc[4][2], A4, bp2); fma2(acc[5][2], A5, bp2); fma2(acc[6][2], A6, bp2); fma2(acc[7][2], A7, bp2);
            fma2(acc[4][3], A4, bp3); fma2(acc[5][3], A5, bp3); fma2(acc[6][3], A6, bp3); fma2(acc[7][3], A7, bp3);
        }
    }

    #pragma unroll
    for (int half = 0; half < 2; half++) {
        #pragma unroll
        for (int jp = 0; jp < 2; jp++) {
            int n0 = bn0 + tx * 4 + half * 64 + jp * 2;
            float sc0 = 1.0f, sh0 = 0.0f, sc1 = 1.0f, sh1 = 0.0f;
            if (bnp) {
                float g0 = bnp[n0],     be0 = bnp[N + n0],     mm0 = bnp[2*N + n0],     vv0 = bnp[3*N + n0];
                float g1 = bnp[n0 + 1], be1 = bnp[N + n0 + 1], mm1 = bnp[2*N + n0 + 1], vv1 = bnp[3*N + n0 + 1];
                sc0 = g0 / sqrtf(vv0 + EPSF); sh0 = be0 - mm0 * sc0;
                sc1 = g1 / sqrtf(vv1 + EPSF); sh1 = be1 - mm1 * sc1;
            }
            float bs0 = bias[n0], bs1 = bias[n0 + 1];
            #pragma unroll
            for (int i = 0; i < 8; i++) {
                int m = bm0 + ty * 4 + ((i < 4) ? i : (64 + i - 4));
                float2 v = unpack2(acc[i][half * 2 + jp]);
                float2 o;
                o.x = (v.x + bs0) * sc0 + sh0;
                o.y = (v.y + bs1) * sc1 + sh1;
                *(float2*)&Out[(size_t)m * N + n0] = o;
            }
        }
    }
}

// ---------------- bf16 tensor-core GEMM for binary-spike A -------------------
// Out[m,n] = (sum_k A[m,k]*(hi+mi+lo)[n,k] + bias[n]) * bn_sc + bn_sh
// A: [M,K] bf16 in {0,1} -> every product exact; fp32 accumulate.
// Tile 128x64x32; 256 thr = 8 warps (4 m x 2 n), warp tile 32x32.
#define GBM 128
#define GBN 64
#define GBK 32
#define ASTR 40   // smem row stride in halves (80B -> conflict-free frag loads)
__global__ void __launch_bounds__(256) gemm_spike_bf16(
    const __nv_bfloat16* __restrict__ A,
    const __nv_bfloat16* __restrict__ Whi, const __nv_bfloat16* __restrict__ Wmi,
    const __nv_bfloat16* __restrict__ Wlo,
    const float* __restrict__ bias, const float* __restrict__ bnp,
    float* __restrict__ Out, int M, int N, int K)
{
    __shared__ __align__(16) unsigned short As[GBM * ASTR];
    __shared__ __align__(16) unsigned short Bs[3][GBN * ASTR];

    int tid = threadIdx.x;
    int wid = tid >> 5, lane = tid & 31;
    int wm = wid & 3, wn = wid >> 2;            // warp origin (wm*32, wn*32)
    int bn0 = blockIdx.x * GBN, bm0 = blockIdx.y * GBM;

    const __nv_bfloat16* Wsel[3] = {Whi, Wmi, Wlo};

    float acc[2][4][4];
    #pragma unroll
    for (int mt = 0; mt < 2; mt++)
        #pragma unroll
        for (int nt = 0; nt < 4; nt++)
            #pragma unroll
            for (int q = 0; q < 4; q++) acc[mt][nt][q] = 0.0f;

    // A tile loads: 128 rows x 8 uint2 (4 halves each) = 1024 -> 4 per thread
    int arow[4], ac2[4];
    #pragma unroll
    for (int j = 0; j < 4; j++) { int idx = tid + j * 256; arow[j] = idx >> 3; ac2[j] = idx & 7; }
    // B tile loads: 3 splits x 64 rows x 8 uint2 = 1536 -> 6 per thread
    int bsp[6], brow[6], bc2[6];
    #pragma unroll
    for (int j = 0; j < 6; j++) {
        int idx = tid + j * 256;
        bsp[j] = idx >> 9; int rem = idx & 511;
        brow[j] = rem >> 3; bc2[j] = rem & 7;
    }

    uint2 pa[4], pb[6];
    #pragma unroll
    for (int j = 0; j < 4; j++)
        pa[j] = *(const uint2*)&A[(size_t)(bm0 + arow[j]) * K + ac2[j] * 4];
    #pragma unroll
    for (int j = 0; j < 6; j++)
        pb[j] = *(const uint2*)&Wsel[bsp[j]][(size_t)(bn0 + brow[j]) * K + bc2[j] * 4];

    for (int k0 = 0; k0 < K; k0 += GBK) {
        __syncthreads();
        #pragma unroll
        for (int j = 0; j < 4; j++)
            *(uint2*)&As[arow[j] * ASTR + ac2[j] * 4] = pa[j];
        #pragma unroll
        for (int j = 0; j < 6; j++)
            *(uint2*)&Bs[bsp[j]][brow[j] * ASTR + bc2[j] * 4] = pb[j];
        __syncthreads();

        if (k0 + GBK < K) {
            #pragma unroll
            for (int j = 0; j < 4; j++)
                pa[j] = *(const uint2*)&A[(size_t)(bm0 + arow[j]) * K + k0 + GBK + ac2[j] * 4];
            #pragma unroll
            for (int j = 0; j < 6; j++)
                pb[j] = *(const uint2*)&Wsel[bsp[j]][(size_t)(bn0 + brow[j]) * K + k0 + GBK + bc2[j] * 4];
        }

        int r4 = lane >> 2, c2 = (lane & 3) * 2;
        #pragma unroll
        for (int ks = 0; ks < 2; ks++) {
            int kc = ks * 16 + c2;
            uint32 afrag[2][4];
            #pragma unroll
            for (int mt = 0; mt < 2; mt++) {
                int mr = wm * 32 + mt * 16 + r4;
                afrag[mt][0] = *(const uint32*)&As[mr * ASTR + kc];
                afrag[mt][1] = *(const uint32*)&As[(mr + 8) * ASTR + kc];
                afrag[mt][2] = *(const uint32*)&As[mr * ASTR + kc + 8];
                afrag[mt][3] = *(const uint32*)&As[(mr + 8) * ASTR + kc + 8];
            }
            #pragma unroll
            for (int s = 0; s < 3; s++) {
                #pragma unroll
                for (int nt = 0; nt < 4; nt++) {
                    int nr = wn * 32 + nt * 8 + r4;
                    uint32 b0 = *(const uint32*)&Bs[s][nr * ASTR + kc];
                    uint32 b1 = *(const uint32*)&Bs[s][nr * ASTR + kc + 8];
                    mma_bf16(acc[0][nt], afrag[0], b0, b1);
                    mma_bf16(acc[1][nt], afrag[1], b0, b1);
                }
            }
        }
    }

    // epilogue
    int r4 = lane >> 2, c2 = (lane & 3) * 2;
    #pragma unroll
    for (int nt = 0; nt < 4; nt++) {
        int n0 = bn0 + wn * 32 + nt * 8 + c2;
        float g0 = bnp[n0],     be0 = bnp[N + n0],     mm0 = bnp[2*N + n0],     vv0 = bnp[3*N + n0];
        float g1 = bnp[n0 + 1], be1 = bnp[N + n0 + 1], mm1 = bnp[2*N + n0 + 1], vv1 = bnp[3*N + n0 + 1];
        float sc0 = g0 / sqrtf(vv0 + EPSF), sh0 = be0 - mm0 * sc0;
        float sc1 = g1 / sqrtf(vv1 + EPSF), sh1 = be1 - mm1 * sc1;
        float bs0 = bias[n0], bs1 = bias[n0 + 1];
        #pragma unroll
        for (int mt = 0; mt < 2; mt++) {
            int m0 = bm0 + wm * 32 + mt * 16 + r4;
            float2 o0, o1;
            o0.x = (acc[mt][nt][0] + bs0) * sc0 + sh0;
            o0.y = (acc[mt][nt][1] + bs1) * sc1 + sh1;
            o1.x = (acc[mt][nt][2] + bs0) * sc0 + sh0;
            o1.y = (acc[mt][nt][3] + bs1) * sc1 + sh1;
            *(float2*)&Out[(size_t)m0 * N + n0] = o0;
            *(float2*)&Out[(size_t)(m0 + 8) * N + n0] = o1;
        }
    }
}

// ---------------- LIF scan (templated output type) ----------------
template<typename OutT>
__global__ void __launch_bounds__(256) lif_kernel(
    const float* __restrict__ X, int ldx,
    const float* __restrict__ Mul, int ldm,
    const float* __restrict__ bnp,
    OutT* __restrict__ S)
{
    int j = blockIdx.x * blockDim.x + threadIdx.x;
    if (j >= B_DIM * C_DIM) return;
    int b = j / C_DIM, c = j % C_DIM;

    float sc = 1.0f, sh = 0.0f;
    if (bnp) {
        float g = bnp[c], be = bnp[C_DIM + c], mm = bnp[2 * C_DIM + c], vv = bnp[3 * C_DIM + c];
        sc = g / sqrtf(vv + EPSF);
        sh = be - mm * sc;
    }

    const float* xp = X + (size_t)b * ldx + c;
    const float* mp = Mul ? (Mul + (size_t)b * ldm + c) : nullptr;
    OutT* sp = S + (size_t)j;
    size_t stx = (size_t)B_DIM * ldx;
    size_t stm = (size_t)B_DIM * ldm;
    size_t sts = (size_t)B_DIM * C_DIM;

    float vm = 0.0f;
    #pragma unroll 4
    for (int t = 0; t < T_DIM; t++) {
        float xv = xp[(size_t)t * stx];
        if (mp) xv *= mp[(size_t)t * stm];
        xv = xv * sc + sh;
        vm = vm * 0.5f + xv;
        float s = (vm >= 1.0f) ? 1.0f : 0.0f;
        vm = (s > 0.0f) ? 0.0f : vm;
        sp[(size_t)t * sts] = (OutT)s;
    }
}

// ---------------- depthwise conv over time (K=31, SAME zero pad) ----------------
#define DW_PAD 15
__global__ void __launch_bounds__(256) dw_kernel(
    const float* __restrict__ S1, const float* __restrict__ w,
    const float* __restrict__ bvec, float* __restrict__ Dout)
{
    __shared__ float sx[T_DIM + 2 * DW_PAD][64];
    int b  = blockIdx.x;
    int c0 = blockIdx.y * 64;
    int tid = threadIdx.x;

    for (int i = tid; i < 2 * DW_PAD * 64; i += 256) {
        int r = i >> 6, ci = i & 63;
        if (r < DW_PAD) sx[r][ci] = 0.0f;
        else            sx[T_DIM + DW_PAD + (r - DW_PAD)][ci] = 0.0f;
    }
    for (int i = tid; i < T_DIM * 64; i += 256) {
        int t = i >> 6, ci = i & 63;
        sx[t + DW_PAD][ci] = S1[((size_t)t * B_DIM + b) * C_DIM + c0 + ci];
    }
    __syncthreads();

    int ci = tid & 63;
    int tg = tid >> 6;
    int c  = c0 + ci;
    int t0 = tg * 32;

    float wr[K_DW];
    #pragma unroll
    for (int k = 0; k < K_DW; k++) wr[k] = w[c * K_DW + k];
    float bb = bvec[c];

    float acc[32];
    #pragma unroll
    for (int i = 0; i < 32; i++) acc[i] = bb;

    #pragma unroll
    for (int dt = -DW_PAD; dt <= 31 + DW_PAD; dt++) {
        float sv = sx[t0 + dt + DW_PAD][ci];
        #pragma unroll
        for (int i = 0; i < 32; i++) {
            int k = dt - i + DW_PAD;
            if (k >= 0 && k < K_DW) acc[i] += sv * wr[k];
        }
    }

    #pragma unroll
    for (int i = 0; i < 32; i++) {
        int t = t0 + i;
        Dout[((size_t)t * B_DIM + b) * C_DIM + c] = acc[i];
    }
}

// ---------------- launch ----------------
extern "C" void kernel_launch(void* const* d_in, const int* in_sizes, int n_in,
                              void* d_out, int out_size)
{
    const float* x        = (const float*)d_in[0];
    const float* ln_g     = (const float*)d_in[1];
    const float* ln_b     = (const float*)d_in[2];
    const float* pw1_w    = (const float*)d_in[3];
    const float* pw1_b    = (const float*)d_in[4];
    const float* bn1_p    = (const float*)d_in[5];
    const float* dw_w     = (const float*)d_in[6];
    const float* dw_b     = (const float*)d_in[7];
    const float* bn2_p    = (const float*)d_in[8];
    const float* pw2_w    = (const float*)d_in[9];
    const float* pw2_b    = (const float*)d_in[10];
    const float* bn3_p    = (const float*)d_in[11];
    const float* gsu_w    = (const float*)d_in[12];
    const float* gsu_b    = (const float*)d_in[13];
    const float* gsu_bn_p = (const float*)d_in[14];

    float *H, *Y1, *S1, *D, *Y2, *Y3, *Sg2;
    __nv_bfloat16 *S2b, *Sgb, *W2hi, *W2mi, *W2lo, *Wghi, *Wgmi, *Wglo;
    cudaGetSymbolAddress((void**)&H,    g_H);
    cudaGetSymbolAddress((void**)&Y1,   g_Y1);
    cudaGetSymbolAddress((void**)&S1,   g_S1);
    cudaGetSymbolAddress((void**)&D,    g_D);
    cudaGetSymbolAddress((void**)&Y2,   g_Y2);
    cudaGetSymbolAddress((void**)&Y3,   g_Y3);
    cudaGetSymbolAddress((void**)&Sg2,  g_Sg2);
    cudaGetSymbolAddress((void**)&S2b,  g_S2b);
    cudaGetSymbolAddress((void**)&Sgb,  g_Sgb);
    cudaGetSymbolAddress((void**)&W2hi, g_W2hi);
    cudaGetSymbolAddress((void**)&W2mi, g_W2mi);
    cudaGetSymbolAddress((void**)&W2lo, g_W2lo);
    cudaGetSymbolAddress((void**)&Wghi, g_Wghi);
    cudaGetSymbolAddress((void**)&Wgmi, g_Wgmi);
    cudaGetSymbolAddress((void**)&Wglo, g_Wglo);

    const int lif_blocks = (B_DIM * C_DIM + 255) / 256;   // 192

    // 0) weight splits
    split_w_kernel<<<(2 * C_DIM * C_DIM + 255) / 256, 256>>>(pw2_w, W2hi, W2mi, W2lo, 2 * C_DIM * C_DIM);
    split_w_kernel<<<(C_DIM * C_DIM + 255) / 256, 256>>>(gsu_w, Wghi, Wgmi, Wglo, C_DIM * C_DIM);

    // 1) LayerNorm
    ln_kernel<<<M_DIM, 256>>>(x, ln_g, ln_b, H);

    // 2) pw1 + bias + bn1 (FFMA2 path)
    gemm_bias_bn<<<dim3(C_DIM / BN, M_DIM / BM), 256>>>(
        H, pw1_w, pw1_b, bn1_p, Y1, M_DIM, C_DIM, C_DIM);

    // 3) LIF -> S1 (fp32)
    lif_kernel<float><<<lif_blocks, 256>>>(Y1, C_DIM, nullptr, 0, nullptr, S1);

    // 4) depthwise over time
    dw_kernel<<<dim3(B_DIM, C_DIM / 64), 256>>>(S1, dw_w, dw_b, D);

    // 5) BN2 + LIF -> S2 (bf16)
    lif_kernel<__nv_bfloat16><<<lif_blocks, 256>>>(D, C_DIM, nullptr, 0, bn2_p, S2b);

    // 6) pw2 + bias + bn3 (tensor cores, split weights)
    gemm_spike_bf16<<<dim3(2 * C_DIM / GBN, M_DIM / GBM), 256>>>(
        S2b, W2hi, W2mi, W2lo, pw2_b, bn3_p, Y2, M_DIM, 2 * C_DIM, C_DIM);

    // 7) LIF(gate half) -> Sg (bf16)
    lif_kernel<__nv_bfloat16><<<lif_blocks, 256>>>(Y2 + C_DIM, 2 * C_DIM, nullptr, 0, nullptr, Sgb);

    // 8) gsu GEMM + bias + gsu_bn (tensor cores)
    gemm_spike_bf16<<<dim3(C_DIM / GBN, M_DIM / GBM), 256>>>(
        Sgb, Wghi, Wgmi, Wglo, gsu_b, gsu_bn_p, Y3, M_DIM, C_DIM, C_DIM);

    // 9) LIF -> Sg2 (fp32)
    lif_kernel<float><<<lif_blocks, 256>>>(Y3, C_DIM, nullptr, 0, nullptr, Sg2);

    // 10) final LIF on out*Sg2 -> d_out
    lif_kernel<float><<<lif_blocks, 256>>>(Y2, 2 * C_DIM, Sg2, C_DIM, nullptr, (float*)d_out);
}

// round 7
// speedup vs baseline: 2.0427x; 1.1130x over previous
#include <cuda_runtime.h>
#include <cuda_bf16.h>
#include <math.h>

#define T_DIM 128
#define B_DIM 64
#define C_DIM 768
#define M_DIM (T_DIM * B_DIM)   // 8192
#define K_DW  31
#define EPSF  1e-5f

typedef unsigned long long ull;
typedef unsigned int uint32;

// ---------------- scratch ----------------
__device__ float g_H  [M_DIM * C_DIM];
__device__ float g_Y1 [M_DIM * C_DIM];
__device__ float g_S1 [M_DIM * C_DIM];
__device__ float g_D  [M_DIM * C_DIM];
__device__ float g_Y2 [M_DIM * 2 * C_DIM];
__device__ float g_Y3 [M_DIM * C_DIM];
__device__ float g_Sg2[M_DIM * C_DIM];
__device__ __nv_bfloat16 g_S2b[M_DIM * C_DIM];
__device__ __nv_bfloat16 g_Sgb[M_DIM * C_DIM];
__device__ __nv_bfloat16 g_W2hi[2 * C_DIM * C_DIM];
__device__ __nv_bfloat16 g_W2mi[2 * C_DIM * C_DIM];
__device__ __nv_bfloat16 g_W2lo[2 * C_DIM * C_DIM];
__device__ __nv_bfloat16 g_Wghi[C_DIM * C_DIM];
__device__ __nv_bfloat16 g_Wgmi[C_DIM * C_DIM];
__device__ __nv_bfloat16 g_Wglo[C_DIM * C_DIM];

// ---------------- packed f32x2 helpers ----------------
__device__ __forceinline__ ull dup2(float v) {
    ull r; asm("mov.b64 %0, {%1, %1};" : "=l"(r) : "f"(v)); return r;
}
__device__ __forceinline__ ull pack2(float lo, float hi) {
    ull r; asm("mov.b64 %0, {%1, %2};" : "=l"(r) : "f"(lo), "f"(hi)); return r;
}
__device__ __forceinline__ void fma2(ull &d, ull a, ull b) {
    asm("fma.rn.f32x2 %0, %1, %2, %0;" : "+l"(d) : "l"(a), "l"(b));
}
__device__ __forceinline__ float2 unpack2(ull v) {
    float2 r; asm("mov.b64 {%0, %1}, %2;" : "=f"(r.x), "=f"(r.y) : "l"(v)); return r;
}

// ---------------- mma / ldmatrix / cp.async helpers ----------------
__device__ __forceinline__ void mma_bf16(float* c, const uint32* a, uint32 b0, uint32 b1) {
    asm volatile(
        "mma.sync.aligned.m16n8k16.row.col.f32.bf16.bf16.f32 "
        "{%0,%1,%2,%3}, {%4,%5,%6,%7}, {%8,%9}, {%0,%1,%2,%3};"
        : "+f"(c[0]), "+f"(c[1]), "+f"(c[2]), "+f"(c[3])
        : "r"(a[0]), "r"(a[1]), "r"(a[2]), "r"(a[3]), "r"(b0), "r"(b1));
}
__device__ __forceinline__ void ldsm4(uint32* r, uint32 saddr) {
    asm volatile("ldmatrix.sync.aligned.m8n8.x4.shared.b16 {%0,%1,%2,%3}, [%4];"
        : "=r"(r[0]), "=r"(r[1]), "=r"(r[2]), "=r"(r[3]) : "r"(saddr));
}
#define CP16(dst, src) \
    asm volatile("cp.async.cg.shared.global [%0], [%1], 16;" :: "r"(dst), "l"(src))
#define CP_COMMIT() asm volatile("cp.async.commit_group;" ::: "memory")
#define CP_WAIT1()  asm volatile("cp.async.wait_group 1;" ::: "memory")

// ---------------- weight split ----------------
__global__ void __launch_bounds__(256) split_w_kernel(
    const float* __restrict__ W,
    __nv_bfloat16* __restrict__ hi, __nv_bfloat16* __restrict__ mi,
    __nv_bfloat16* __restrict__ lo, int n)
{
    int i = blockIdx.x * blockDim.x + threadIdx.x;
    if (i >= n) return;
    float w = W[i];
    __nv_bfloat16 h = __float2bfloat16(w);
    float r1 = w - __bfloat162float(h);
    __nv_bfloat16 m = __float2bfloat16(r1);
    float r2 = r1 - __bfloat162float(m);
    hi[i] = h; mi[i] = m; lo[i] = __float2bfloat16(r2);
}

// ---------------- block reduction helper ----------------
__inline__ __device__ float block_reduce_sum(float val, float* shmem) {
    int tid = threadIdx.x;
    #pragma unroll
    for (int o = 16; o > 0; o >>= 1) val += __shfl_xor_sync(0xffffffffu, val, o);
    if ((tid & 31) == 0) shmem[tid >> 5] = val;
    __syncthreads();
    float r = 0.0f;
    if (tid < 8) r = shmem[tid];
    if (tid < 32) {
        #pragma unroll
        for (int o = 4; o > 0; o >>= 1) r += __shfl_xor_sync(0xffffffffu, r, o);
    }
    if (tid == 0) shmem[0] = r;
    __syncthreads();
    r = shmem[0];
    __syncthreads();
    return r;
}

// ---------------- layernorm ----------------
__global__ void __launch_bounds__(256) ln_kernel(
    const float* __restrict__ x, const float* __restrict__ gam,
    const float* __restrict__ bet, float* __restrict__ out)
{
    __shared__ float red[32];
    int row = blockIdx.x;
    const float* xr = x + (size_t)row * C_DIM;
    float* orow = out + (size_t)row * C_DIM;
    int tid = threadIdx.x;

    float lx[3];
    float s = 0.0f;
    #pragma unroll
    for (int i = 0; i < 3; i++) { lx[i] = xr[tid + i * 256]; s += lx[i]; }
    float mean = block_reduce_sum(s, red) * (1.0f / C_DIM);

    float s2 = 0.0f;
    #pragma unroll
    for (int i = 0; i < 3; i++) { float d = lx[i] - mean; s2 += d * d; }
    float var = block_reduce_sum(s2, red) * (1.0f / C_DIM);
    float rstd = 1.0f / sqrtf(var + EPSF);

    #pragma unroll
    for (int i = 0; i < 3; i++) {
        int c = tid + i * 256;
        orow[c] = (lx[i] - mean) * rstd * gam[c] + bet[c];
    }
}

// ---------------- fp32 GEMM via packed FFMA2 (GEMM1) ----------------
#define BM 128
#define BN 128
#define BK 16
__global__ void __launch_bounds__(256) gemm_bias_bn(
    const float* __restrict__ A, const float* __restrict__ W,
    const float* __restrict__ bias, const float* __restrict__ bnp,
    float* __restrict__ Out, int M, int N, int K)
{
    __shared__ float As[BK][BM + 4];
    __shared__ float Bs[BK][BN + 4];

    int tid = threadIdx.x;
    int bn0 = blockIdx.x * BN;
    int bm0 = blockIdx.y * BM;
    int tx = tid & 15;
    int ty = tid >> 4;

    int lr = tid & 127;
    int lk = (tid >> 7) * 8;
    const float* Ap = A + (size_t)(bm0 + lr) * K + lk;
    const float* Wp = W + (size_t)(bn0 + lr) * K + lk;

    ull acc[8][4];
    #pragma unroll
    for (int i = 0; i < 8; i++)
        #pragma unroll
        for (int j = 0; j < 4; j++) acc[i][j] = 0ull;

    float4 pa0 = *(const float4*)(Ap);
    float4 pa1 = *(const float4*)(Ap + 4);
    float4 pb0 = *(const float4*)(Wp);
    float4 pb1 = *(const float4*)(Wp + 4);

    for (int k0 = 0; k0 < K; k0 += BK) {
        __syncthreads();
        As[lk + 0][lr] = pa0.x; As[lk + 1][lr] = pa0.y;
        As[lk + 2][lr] = pa0.z; As[lk + 3][lr] = pa0.w;
        As[lk + 4][lr] = pa1.x; As[lk + 5][lr] = pa1.y;
        As[lk + 6][lr] = pa1.z; As[lk + 7][lr] = pa1.w;
        Bs[lk + 0][lr] = pb0.x; Bs[lk + 1][lr] = pb0.y;
        Bs[lk + 2][lr] = pb0.z; Bs[lk + 3][lr] = pb0.w;
        Bs[lk + 4][lr] = pb1.x; Bs[lk + 5][lr] = pb1.y;
        Bs[lk + 6][lr] = pb1.z; Bs[lk + 7][lr] = pb1.w;
        __syncthreads();

        if (k0 + BK < K) {
            pa0 = *(const float4*)(Ap + k0 + BK);
            pa1 = *(const float4*)(Ap + k0 + BK + 4);
            pb0 = *(const float4*)(Wp + k0 + BK);
            pb1 = *(const float4*)(Wp + k0 + BK + 4);
        }

        #pragma unroll
        for (int kk = 0; kk < BK; kk++) {
            float4 av0 = *(const float4*)&As[kk][ty * 4];
            float4 av1 = *(const float4*)&As[kk][ty * 4 + 64];
            float4 bv0 = *(const float4*)&Bs[kk][tx * 4];
            float4 bv1 = *(const float4*)&Bs[kk][tx * 4 + 64];
            ull bp0 = pack2(bv0.x, bv0.y);
            ull bp1 = pack2(bv0.z, bv0.w);
            ull bp2 = pack2(bv1.x, bv1.y);
            ull bp3 = pack2(bv1.z, bv1.w);
            ull A0 = dup2(av0.x), A1 = dup2(av0.y), A2 = dup2(av0.z), A3 = dup2(av0.w);
            fma2(acc[0][0], A0, bp0); fma2(acc[1][0], A1, bp0); fma2(acc[2][0], A2, bp0); fma2(acc[3][0], A3, bp0);
            fma2(acc[0][1], A0, bp1); fma2(acc[1][1], A1, bp1); fma2(acc[2][1], A2, bp1); fma2(acc[3][1], A3, bp1);
            fma2(acc[0][2], A0, bp2); fma2(acc[1][2], A1, bp2); fma2(acc[2][2], A2, bp2); fma2(acc[3][2], A3, bp2);
            fma2(acc[0][3], A0, bp3); fma2(acc[1][3], A1, bp3); fma2(acc[2][3], A2, bp3); fma2(acc[3][3], A3, bp3);
            ull A4 = dup2(av1.x), A5 = dup2(av1.y), A6 = dup2(av1.z), A7 = dup2(av1.w);
            fma2(acc[4][0], A4, bp0); fma2(acc[5][0], A5, bp0); fma2(acc[6][0], A6, bp0); fma2(acc[7][0], A7, bp0);
            fma2(acc[4][1], A4, bp1); fma2(acc[5][1], A5, bp1); fma2(acc[6][1], A6, bp1); fma2(acc[7][1], A7, bp1);
            fma2(acc[4][2], A4, bp2); fma2(acc[5][2], A5, bp2); fma2(acc[6][2], A6, bp2); fma2(acc[7][2], A7, bp2);
            fma2(acc[4][3], A4, bp3); fma2(acc[5][3], A5, bp3); fma2(acc[6][3], A6, bp3); fma2(acc[7][3], A7, bp3);
        }
    }

    #pragma unroll
    for (int half = 0; half < 2; half++) {
        #pragma unroll
        for (int jp = 0; jp < 2; jp++) {
            int n0 = bn0 + tx * 4 + half * 64 + jp * 2;
            float sc0 = 1.0f, sh0 = 0.0f, sc1 = 1.0f, sh1 = 0.0f;
            if (bnp) {
                float g0 = bnp[n0],     be0 = bnp[N + n0],     mm0 = bnp[2*N + n0],     vv0 = bnp[3*N + n0];
                float g1 = bnp[n0 + 1], be1 = bnp[N + n0 + 1], mm1 = bnp[2*N + n0 + 1], vv1 = bnp[3*N + n0 + 1];
                sc0 = g0 / sqrtf(vv0 + EPSF); sh0 = be0 - mm0 * sc0;
                sc1 = g1 / sqrtf(vv1 + EPSF); sh1 = be1 - mm1 * sc1;
            }
            float bs0 = bias[n0], bs1 = bias[n0 + 1];
            #pragma unroll
            for (int i = 0; i < 8; i++) {
                int m = bm0 + ty * 4 + ((i < 4) ? i : (64 + i - 4));
                float2 v = unpack2(acc[i][half * 2 + jp]);
                float2 o;
                o.x = (v.x + bs0) * sc0 + sh0;
                o.y = (v.y + bs1) * sc1 + sh1;
                *(float2*)&Out[(size_t)m * N + n0] = o;
            }
        }
    }
}

// ---------------- bf16 tensor-core GEMM for binary-spike A -------------------
// ldmatrix fragment loads + 2-stage cp.async pipeline.
// Tile 128x64x32; 8 warps (4m x 2n), warp tile 32x32. 3 weight splits.
#define GBM 128
#define GBN 64
#define GBK 32
#define ASTR 40                       // halves; 80B row stride (16B-aligned, conflict-free)
#define AH   (GBM * ASTR)             // 5120 halves
#define BH   (GBN * ASTR)             // 2560 halves
#define STG  (AH + 3 * BH)            // 12800 halves per stage
#define SPIKE_SMEM (2 * STG * 2)      // 51200 bytes

__global__ void __launch_bounds__(256) gemm_spike_bf16(
    const __nv_bfloat16* __restrict__ A,
    const __nv_bfloat16* __restrict__ Whi, const __nv_bfloat16* __restrict__ Wmi,
    const __nv_bfloat16* __restrict__ Wlo,
    const float* __restrict__ bias, const float* __restrict__ bnp,
    float* __restrict__ Out, int M, int N, int K)
{
    extern __shared__ __align__(16) unsigned short sm[];
    uint32 smb = (uint32)__cvta_generic_to_shared(sm);

    int tid = threadIdx.x;
    int wid = tid >> 5, lane = tid & 31;
    int wm = wid & 3, wn = wid >> 2;
    int bn0 = blockIdx.x * GBN, bm0 = blockIdx.y * GBM;

    // cp.async mapping: row = tid>>2 (+64j for A), col = (tid&3)*8 halves
    int ldrow = tid >> 2;
    int ldcol = (tid & 3) * 8;

    float acc[2][4][4];
    #pragma unroll
    for (int mt = 0; mt < 2; mt++)
        #pragma unroll
        for (int nt = 0; nt < 4; nt++)
            #pragma unroll
            for (int q = 0; q < 4; q++) acc[mt][nt][q] = 0.0f;

    // ldmatrix per-lane row/col offsets
    int a_row = (lane & 7) + ((lane >> 3) & 1) * 8;     // within m16 tile
    int a_ko  = ((lane >> 4) & 1) * 8;
    int b_row = (lane & 7) + ((lane >> 4) & 1) * 8;     // within n16 group
    int b_ko  = ((lane >> 3) & 1) * 8;

    auto issue = [&](int st, int k0) {
        #pragma unroll
        for (int j = 0; j < 2; j++) {
            int row = ldrow + j * 64;
            uint32 dst = smb + (uint32)(st * STG + row * ASTR + ldcol) * 2;
            const __nv_bfloat16* src = A + (size_t)(bm0 + row) * K + k0 + ldcol;
            CP16(dst, src);
        }
        {
            uint32 dst = smb + (uint32)(st * STG + AH + ldrow * ASTR + ldcol) * 2;
            CP16(dst, Whi + (size_t)(bn0 + ldrow) * K + k0 + ldcol);
            dst += (uint32)BH * 2;
            CP16(dst, Wmi + (size_t)(bn0 + ldrow) * K + k0 + ldcol);
            dst += (uint32)BH * 2;
            CP16(dst, Wlo + (size_t)(bn0 + ldrow) * K + k0 + ldcol);
        }
    };

    int NCH = K / GBK;
    issue(0, 0);
    CP_COMMIT();

    for (int ch = 0; ch < NCH; ch++) {
        if (ch + 1 < NCH) issue((ch + 1) & 1, (ch + 1) * GBK);
        CP_COMMIT();
        CP_WAIT1();
        __syncthreads();

        int st = ch & 1;
        uint32 abase = smb + (uint32)(st * STG) * 2;
        uint32 bbase = smb + (uint32)(st * STG + AH) * 2;

        #pragma unroll
        for (int ks = 0; ks < 2; ks++) {
            int kc = ks * 16;
            uint32 af[2][4];
            #pragma unroll
            for (int mt = 0; mt < 2; mt++) {
                uint32 ad = abase + (uint32)((wm * 32 + mt * 16 + a_row) * ASTR + kc + a_ko) * 2;
                ldsm4(af[mt], ad);
            }
            #pragma unroll
            for (int s = 0; s < 3; s++) {
                #pragma unroll
                for (int g = 0; g < 2; g++) {
                    uint32 bf[4];
                    uint32 bd = bbase + (uint32)(s * BH + (wn * 32 + g * 16 + b_row) * ASTR + kc + b_ko) * 2;
                    ldsm4(bf, bd);
                    mma_bf16(acc[0][2 * g],     af[0], bf[0], bf[1]);
                    mma_bf16(acc[1][2 * g],     af[1], bf[0], bf[1]);
                    mma_bf16(acc[0][2 * g + 1], af[0], bf[2], bf[3]);
                    mma_bf16(acc[1][2 * g + 1], af[1], bf[2], bf[3]);
                }
            }
        }
        __syncthreads();
    }

    // epilogue: bias + BN affine
    int r4 = lane >> 2, c2 = (lane & 3) * 2;
    #pragma unroll
    for (int nt = 0; nt < 4; nt++) {
        int n0 = bn0 + wn * 32 + nt * 8 + c2;
        float g0 = bnp[n0],     be0 = bnp[N + n0],     mm0 = bnp[2*N + n0],     vv0 = bnp[3*N + n0];
        float g1 = bnp[n0 + 1], be1 = bnp[N + n0 + 1], mm1 = bnp[2*N + n0 + 1], vv1 = bnp[3*N + n0 + 1];
        float sc0 = g0 / sqrtf(vv0 + EPSF), sh0 = be0 - mm0 * sc0;
        float sc1 = g1 / sqrtf(vv1 + EPSF), sh1 = be1 - mm1 * sc1;
        float bs0 = bias[n0], bs1 = bias[n0 + 1];
        #pragma unroll
        for (int mt = 0; mt < 2; mt++) {
            int m0 = bm0 + wm * 32 + mt * 16 + r4;
            float2 o0, o1;
            o0.x = (acc[mt][nt][0] + bs0) * sc0 + sh0;
            o0.y = (acc[mt][nt][1] + bs1) * sc1 + sh1;
            o1.x = (acc[mt][nt][2] + bs0) * sc0 + sh0;
            o1.y = (acc[mt][nt][3] + bs1) * sc1 + sh1;
            *(float2*)&Out[(size_t)m0 * N + n0] = o0;
            *(float2*)&Out[(size_t)(m0 + 8) * N + n0] = o1;
        }
    }
}

// ---------------- LIF scan ----------------
template<typename OutT>
__global__ void __launch_bounds__(256) lif_kernel(
    const float* __restrict__ X, int ldx,
    const float* __restrict__ Mul, int ldm,
    const float* __restrict__ bnp,
    OutT* __restrict__ S)
{
    int j = blockIdx.x * blockDim.x + threadIdx.x;
    if (j >= B_DIM * C_DIM) return;
    int b = j / C_DIM, c = j % C_DIM;

    float sc = 1.0f, sh = 0.0f;
    if (bnp) {
        float g = bnp[c], be = bnp[C_DIM + c], mm = bnp[2 * C_DIM + c], vv = bnp[3 * C_DIM + c];
        sc = g / sqrtf(vv + EPSF);
        sh = be - mm * sc;
    }

    const float* xp = X + (size_t)b * ldx + c;
    const float* mp = Mul ? (Mul + (size_t)b * ldm + c) : nullptr;
    OutT* sp = S + (size_t)j;
    size_t stx = (size_t)B_DIM * ldx;
    size_t stm = (size_t)B_DIM * ldm;
    size_t sts = (size_t)B_DIM * C_DIM;

    float vm = 0.0f;
    #pragma unroll 4
    for (int t = 0; t < T_DIM; t++) {
        float xv = xp[(size_t)t * stx];
        if (mp) xv *= mp[(size_t)t * stm];
        xv = xv * sc + sh;
        vm = vm * 0.5f + xv;
        float s = (vm >= 1.0f) ? 1.0f : 0.0f;
        vm = (s > 0.0f) ? 0.0f : vm;
        sp[(size_t)t * sts] = (OutT)s;
    }
}

// ---------------- depthwise conv over time ----------------
#define DW_PAD 15
__global__ void __launch_bounds__(256) dw_kernel(
    const float* __restrict__ S1, const float* __restrict__ w,
    const float* __restrict__ bvec, float* __restrict__ Dout)
{
    __shared__ float sx[T_DIM + 2 * DW_PAD][64];
    int b  = blockIdx.x;
    int c0 = blockIdx.y * 64;
    int tid = threadIdx.x;

    for (int i = tid; i < 2 * DW_PAD * 64; i += 256) {
        int r = i >> 6, ci = i & 63;
        if (r < DW_PAD) sx[r][ci] = 0.0f;
        else            sx[T_DIM + DW_PAD + (r - DW_PAD)][ci] = 0.0f;
    }
    for (int i = tid; i < T_DIM * 64; i += 256) {
        int t = i >> 6, ci = i & 63;
        sx[t + DW_PAD][ci] = S1[((size_t)t * B_DIM + b) * C_DIM + c0 + ci];
    }
    __syncthreads();

    int ci = tid & 63;
    int tg = tid >> 6;
    int c  = c0 + ci;
    int t0 = tg * 32;

    float wr[K_DW];
    #pragma unroll
    for (int k = 0; k < K_DW; k++) wr[k] = w[c * K_DW + k];
    float bb = bvec[c];

    float acc[32];
    #pragma unroll
    for (int i = 0; i < 32; i++) acc[i] = bb;

    #pragma unroll
    for (int dt = -DW_PAD; dt <= 31 + DW_PAD; dt++) {
        float sv = sx[t0 + dt + DW_PAD][ci];
        #pragma unroll
        for (int i = 0; i < 32; i++) {
            int k = dt - i + DW_PAD;
            if (k >= 0 && k < K_DW) acc[i] += sv * wr[k];
        }
    }

    #pragma unroll
    for (int i = 0; i < 32; i++) {
        int t = t0 + i;
        Dout[((size_t)t * B_DIM + b) * C_DIM + c] = acc[i];
    }
}

// ---------------- launch ----------------
extern "C" void kernel_launch(void* const* d_in, const int* in_sizes, int n_in,
                              void* d_out, int out_size)
{
    const float* x        = (const float*)d_in[0];
    const float* ln_g     = (const float*)d_in[1];
    const float* ln_b     = (const float*)d_in[2];
    const float* pw1_w    = (const float*)d_in[3];
    const float* pw1_b    = (const float*)d_in[4];
    const float* bn1_p    = (const float*)d_in[5];
    const float* dw_w     = (const float*)d_in[6];
    const float* dw_b     = (const float*)d_in[7];
    const float* bn2_p    = (const float*)d_in[8];
    const float* pw2_w    = (const float*)d_in[9];
    const float* pw2_b    = (const float*)d_in[10];
    const float* bn3_p    = (const float*)d_in[11];
    const float* gsu_w    = (const float*)d_in[12];
    const float* gsu_b    = (const float*)d_in[13];
    const float* gsu_bn_p = (const float*)d_in[14];

    float *H, *Y1, *S1, *D, *Y2, *Y3, *Sg2;
    __nv_bfloat16 *S2b, *Sgb, *W2hi, *W2mi, *W2lo, *Wghi, *Wgmi, *Wglo;
    cudaGetSymbolAddress((void**)&H,    g_H);
    cudaGetSymbolAddress((void**)&Y1,   g_Y1);
    cudaGetSymbolAddress((void**)&S1,   g_S1);
    cudaGetSymbolAddress((void**)&D,    g_D);
    cudaGetSymbolAddress((void**)&Y2,   g_Y2);
    cudaGetSymbolAddress((void**)&Y3,   g_Y3);
    cudaGetSymbolAddress((void**)&Sg2,  g_Sg2);
    cudaGetSymbolAddress((void**)&S2b,  g_S2b);
    cudaGetSymbolAddress((void**)&Sgb,  g_Sgb);
    cudaGetSymbolAddress((void**)&W2hi, g_W2hi);
    cudaGetSymbolAddress((void**)&W2mi, g_W2mi);
    cudaGetSymbolAddress((void**)&W2lo, g_W2lo);
    cudaGetSymbolAddress((void**)&Wghi, g_Wghi);
    cudaGetSymbolAddress((void**)&Wgmi, g_Wgmi);
    cudaGetSymbolAddress((void**)&Wglo, g_Wglo);

    static int smem_set = 0;
    if (!smem_set) {
        cudaFuncSetAttribute(gemm_spike_bf16,
            cudaFuncAttributeMaxDynamicSharedMemorySize, SPIKE_SMEM);
        smem_set = 1;
    }

    const int lif_blocks = (B_DIM * C_DIM + 255) / 256;   // 192

    // 0) weight splits
    split_w_kernel<<<(2 * C_DIM * C_DIM + 255) / 256, 256>>>(pw2_w, W2hi, W2mi, W2lo, 2 * C_DIM * C_DIM);
    split_w_kernel<<<(C_DIM * C_DIM + 255) / 256, 256>>>(gsu_w, Wghi, Wgmi, Wglo, C_DIM * C_DIM);

    // 1) LayerNorm
    ln_kernel<<<M_DIM, 256>>>(x, ln_g, ln_b, H);

    // 2) pw1 + bias + bn1 (FFMA2)
    gemm_bias_bn<<<dim3(C_DIM / BN, M_DIM / BM), 256>>>(
        H, pw1_w, pw1_b, bn1_p, Y1, M_DIM, C_DIM, C_DIM);

    // 3) LIF -> S1
    lif_kernel<float><<<lif_blocks, 256>>>(Y1, C_DIM, nullptr, 0, nullptr, S1);

    // 4) depthwise
    dw_kernel<<<dim3(B_DIM, C_DIM / 64), 256>>>(S1, dw_w, dw_b, D);

    // 5) BN2 + LIF -> S2 (bf16)
    lif_kernel<__nv_bfloat16><<<lif_blocks, 256>>>(D, C_DIM, nullptr, 0, bn2_p, S2b);

    // 6) pw2 + bias + bn3 (tensor)
    gemm_spike_bf16<<<dim3(2 * C_DIM / GBN, M_DIM / GBM), 256, SPIKE_SMEM>>>(
        S2b, W2hi, W2mi, W2lo, pw2_b, bn3_p, Y2, M_DIM, 2 * C_DIM, C_DIM);

    // 7) LIF(gate) -> Sg (bf16)
    lif_kernel<__nv_bfloat16><<<lif_blocks, 256>>>(Y2 + C_DIM, 2 * C_DIM, nullptr, 0, nullptr, Sgb);

    // 8) gsu GEMM (tensor)
    gemm_spike_bf16<<<dim3(C_DIM / GBN, M_DIM / GBM), 256, SPIKE_SMEM>>>(
        Sgb, Wghi, Wgmi, Wglo, gsu_b, gsu_bn_p, Y3, M_DIM, C_DIM, C_DIM);

    // 9) LIF -> Sg2
    lif_kernel<float><<<lif_blocks, 256>>>(Y3, C_DIM, nullptr, 0, nullptr, Sg2);

    // 10) final LIF on out*Sg2 -> d_out
    lif_kernel<float><<<lif_blocks, 256>>>(Y2, 2 * C_DIM, Sg2, C_DIM, nullptr, (float*)d_out);
}

// round 9
// speedup vs baseline: 2.1214x; 1.0386x over previous
#include <cuda_runtime.h>
#include <cuda_bf16.h>
#include <math.h>

#define T_DIM 128
#define B_DIM 64
#define C_DIM 768
#define M_DIM (T_DIM * B_DIM)   // 8192
#define K_DW  31
#define EPSF  1e-5f

typedef unsigned long long ull;
typedef unsigned int uint32;

// ---------------- scratch ----------------
__device__ float g_Y1 [M_DIM * C_DIM];
__device__ float g_S1 [M_DIM * C_DIM];
__device__ float g_D  [M_DIM * C_DIM];
__device__ float g_Y2 [M_DIM * 2 * C_DIM];
__device__ float g_Y3 [M_DIM * C_DIM];
__device__ float g_Sg2[M_DIM * C_DIM];
__device__ __nv_bfloat16 g_S2b[M_DIM * C_DIM];
__device__ __nv_bfloat16 g_Sgb[M_DIM * C_DIM];
// H splits (layernorm out, 3x bf16)
__device__ __nv_bfloat16 g_Hh[M_DIM * C_DIM];
__device__ __nv_bfloat16 g_Hm[M_DIM * C_DIM];
__device__ __nv_bfloat16 g_Hl[M_DIM * C_DIM];
// weight splits (bf16 x3)
__device__ __nv_bfloat16 g_W1hi[C_DIM * C_DIM];
__device__ __nv_bfloat16 g_W1mi[C_DIM * C_DIM];
__device__ __nv_bfloat16 g_W1lo[C_DIM * C_DIM];
__device__ __nv_bfloat16 g_W2hi[2 * C_DIM * C_DIM];
__device__ __nv_bfloat16 g_W2mi[2 * C_DIM * C_DIM];
__device__ __nv_bfloat16 g_W2lo[2 * C_DIM * C_DIM];
__device__ __nv_bfloat16 g_Wghi[C_DIM * C_DIM];
__device__ __nv_bfloat16 g_Wgmi[C_DIM * C_DIM];
__device__ __nv_bfloat16 g_Wglo[C_DIM * C_DIM];

// ---------------- mma / ldmatrix / cp.async helpers ----------------
__device__ __forceinline__ void mma_bf16(float* c, const uint32* a, uint32 b0, uint32 b1) {
    asm volatile(
        "mma.sync.aligned.m16n8k16.row.col.f32.bf16.bf16.f32 "
        "{%0,%1,%2,%3}, {%4,%5,%6,%7}, {%8,%9}, {%0,%1,%2,%3};"
        : "+f"(c[0]), "+f"(c[1]), "+f"(c[2]), "+f"(c[3])
        : "r"(a[0]), "r"(a[1]), "r"(a[2]), "r"(a[3]), "r"(b0), "r"(b1));
}
__device__ __forceinline__ void ldsm4(uint32* r, uint32 saddr) {
    asm volatile("ldmatrix.sync.aligned.m8n8.x4.shared.b16 {%0,%1,%2,%3}, [%4];"
        : "=r"(r[0]), "=r"(r[1]), "=r"(r[2]), "=r"(r[3]) : "r"(saddr));
}
#define CP16(dst, src) \
    asm volatile("cp.async.cg.shared.global [%0], [%1], 16;" :: "r"(dst), "l"(src))
#define CP_COMMIT() asm volatile("cp.async.commit_group;" ::: "memory")
#define CP_WAIT1()  asm volatile("cp.async.wait_group 1;" ::: "memory")

// ---------------- weight split ----------------
__global__ void __launch_bounds__(256) split_w_kernel(
    const float* __restrict__ W,
    __nv_bfloat16* __restrict__ hi, __nv_bfloat16* __restrict__ mi,
    __nv_bfloat16* __restrict__ lo, int n)
{
    int i = blockIdx.x * blockDim.x + threadIdx.x;
    if (i >= n) return;
    float w = W[i];
    __nv_bfloat16 h = __float2bfloat16(w);
    float r1 = w - __bfloat162float(h);
    __nv_bfloat16 m = __float2bfloat16(r1);
    float r2 = r1 - __bfloat162float(m);
    hi[i] = h; mi[i] = m; lo[i] = __float2bfloat16(r2);
}

// ---------------- block reduction helper ----------------
__inline__ __device__ float block_reduce_sum(float val, float* shmem) {
    int tid = threadIdx.x;
    #pragma unroll
    for (int o = 16; o > 0; o >>= 1) val += __shfl_xor_sync(0xffffffffu, val, o);
    if ((tid & 31) == 0) shmem[tid >> 5] = val;
    __syncthreads();
    float r = 0.0f;
    if (tid < 8) r = shmem[tid];
    if (tid < 32) {
        #pragma unroll
        for (int o = 4; o > 0; o >>= 1) r += __shfl_xor_sync(0xffffffffu, r, o);
    }
    if (tid == 0) shmem[0] = r;
    __syncthreads();
    r = shmem[0];
    __syncthreads();
    return r;
}

// ---------------- layernorm -> 3-way bf16 split output ----------------
__global__ void __launch_bounds__(256) ln_kernel(
    const float* __restrict__ x, const float* __restrict__ gam,
    const float* __restrict__ bet,
    __nv_bfloat16* __restrict__ Hh, __nv_bfloat16* __restrict__ Hm,
    __nv_bfloat16* __restrict__ Hl)
{
    __shared__ float red[32];
    int row = blockIdx.x;
    const float* xr = x + (size_t)row * C_DIM;
    int tid = threadIdx.x;

    float lx[3];
    float s = 0.0f;
    #pragma unroll
    for (int i = 0; i < 3; i++) { lx[i] = xr[tid + i * 256]; s += lx[i]; }
    float mean = block_reduce_sum(s, red) * (1.0f / C_DIM);

    float s2 = 0.0f;
    #pragma unroll
    for (int i = 0; i < 3; i++) { float d = lx[i] - mean; s2 += d * d; }
    float var = block_reduce_sum(s2, red) * (1.0f / C_DIM);
    float rstd = 1.0f / sqrtf(var + EPSF);

    #pragma unroll
    for (int i = 0; i < 3; i++) {
        int c = tid + i * 256;
        float y = (lx[i] - mean) * rstd * gam[c] + bet[c];
        __nv_bfloat16 h = __float2bfloat16(y);
        float r1 = y - __bfloat162float(h);
        __nv_bfloat16 m = __float2bfloat16(r1);
        float r2 = r1 - __bfloat162float(m);
        size_t idx = (size_t)row * C_DIM + c;
        Hh[idx] = h; Hm[idx] = m; Hl[idx] = __float2bfloat16(r2);
    }
}

// ================= shared GEMM geometry =================
#define GBM 128
#define GBN 64
#define GBK 32
#define ASTR 40                        // halves; 80B row stride

// ---------------- spike GEMM (binary A, 3 W splits) ----------------
#define AH   (GBM * ASTR)
#define BH   (GBN * ASTR)
#define STG  (AH + 3 * BH)
#define SPIKE_SMEM (2 * STG * 2)

__global__ void __launch_bounds__(256) gemm_spike_bf16(
    const __nv_bfloat16* __restrict__ A,
    const __nv_bfloat16* __restrict__ Whi, const __nv_bfloat16* __restrict__ Wmi,
    const __nv_bfloat16* __restrict__ Wlo,
    const float* __restrict__ bias, const float* __restrict__ bnp,
    float* __restrict__ Out, int M, int N, int K)
{
    extern __shared__ __align__(16) unsigned short sm[];
    uint32 smb = (uint32)__cvta_generic_to_shared(sm);

    int tid = threadIdx.x;
    int wid = tid >> 5, lane = tid & 31;
    int wm = wid & 3, wn = wid >> 2;
    int bn0 = blockIdx.x * GBN, bm0 = blockIdx.y * GBM;

    int ldrow = tid >> 2;
    int ldcol = (tid & 3) * 8;

    float acc[2][4][4];
    #pragma unroll
    for (int mt = 0; mt < 2; mt++)
        #pragma unroll
        for (int nt = 0; nt < 4; nt++)
            #pragma unroll
            for (int q = 0; q < 4; q++) acc[mt][nt][q] = 0.0f;

    int a_row = (lane & 7) + ((lane >> 3) & 1) * 8;
    int a_ko  = ((lane >> 4) & 1) * 8;
    int b_row = (lane & 7) + ((lane >> 4) & 1) * 8;
    int b_ko  = ((lane >> 3) & 1) * 8;

    auto issue = [&](int st, int k0) {
        #pragma unroll
        for (int j = 0; j < 2; j++) {
            int row = ldrow + j * 64;
            uint32 dst = smb + (uint32)(st * STG + row * ASTR + ldcol) * 2;
            CP16(dst, A + (size_t)(bm0 + row) * K + k0 + ldcol);
        }
        uint32 dst = smb + (uint32)(st * STG + AH + ldrow * ASTR + ldcol) * 2;
        CP16(dst, Whi + (size_t)(bn0 + ldrow) * K + k0 + ldcol);
        dst += (uint32)BH * 2;
        CP16(dst, Wmi + (size_t)(bn0 + ldrow) * K + k0 + ldcol);
        dst += (uint32)BH * 2;
        CP16(dst, Wlo + (size_t)(bn0 + ldrow) * K + k0 + ldcol);
    };

    int NCH = K / GBK;
    issue(0, 0);
    CP_COMMIT();

    for (int ch = 0; ch < NCH; ch++) {
        if (ch + 1 < NCH) issue((ch + 1) & 1, (ch + 1) * GBK);
        CP_COMMIT();
        CP_WAIT1();
        __syncthreads();

        int st = ch & 1;
        uint32 abase = smb + (uint32)(st * STG) * 2;
        uint32 bbase = smb + (uint32)(st * STG + AH) * 2;

        #pragma unroll
        for (int ks = 0; ks < 2; ks++) {
            int kc = ks * 16;
            uint32 af[2][4];
            #pragma unroll
            for (int mt = 0; mt < 2; mt++)
                ldsm4(af[mt], abase + (uint32)((wm * 32 + mt * 16 + a_row) * ASTR + kc + a_ko) * 2);
            #pragma unroll
            for (int s = 0; s < 3; s++) {
                #pragma unroll
                for (int g = 0; g < 2; g++) {
                    uint32 bf[4];
                    ldsm4(bf, bbase + (uint32)(s * BH + (wn * 32 + g * 16 + b_row) * ASTR + kc + b_ko) * 2);
                    mma_bf16(acc[0][2 * g],     af[0], bf[0], bf[1]);
                    mma_bf16(acc[1][2 * g],     af[1], bf[0], bf[1]);
                    mma_bf16(acc[0][2 * g + 1], af[0], bf[2], bf[3]);
                    mma_bf16(acc[1][2 * g + 1], af[1], bf[2], bf[3]);
                }
            }
        }
        __syncthreads();
    }

    int r4 = lane >> 2, c2 = (lane & 3) * 2;
    #pragma unroll
    for (int nt = 0; nt < 4; nt++) {
        int n0 = bn0 + wn * 32 + nt * 8 + c2;
        float g0 = bnp[n0],     be0 = bnp[N + n0],     mm0 = bnp[2*N + n0],     vv0 = bnp[3*N + n0];
        float g1 = bnp[n0 + 1], be1 = bnp[N + n0 + 1], mm1 = bnp[2*N + n0 + 1], vv1 = bnp[3*N + n0 + 1];
        float sc0 = g0 / sqrtf(vv0 + EPSF), sh0 = be0 - mm0 * sc0;
        float sc1 = g1 / sqrtf(vv1 + EPSF), sh1 = be1 - mm1 * sc1;
        float bs0 = bias[n0], bs1 = bias[n0 + 1];
        #pragma unroll
        for (int mt = 0; mt < 2; mt++) {
            int m0 = bm0 + wm * 32 + mt * 16 + r4;
            float2 o0, o1;
            o0.x = (acc[mt][nt][0] + bs0) * sc0 + sh0;
            o0.y = (acc[mt][nt][1] + bs1) * sc1 + sh1;
            o1.x = (acc[mt][nt][2] + bs0) * sc0 + sh0;
            o1.y = (acc[mt][nt][3] + bs1) * sc1 + sh1;
            *(float2*)&Out[(size_t)m0 * N + n0] = o0;
            *(float2*)&Out[(size_t)(m0 + 8) * N + n0] = o1;
        }
    }
}

// ---------------- 6-term split GEMM (fp32-accurate, A & W both split) ---------
// Out = bn( sum_{s+t<=2} A_s * W_t^T + bias ).  Error ~2^-33 relative.
#define S6_AH (GBM * ASTR)
#define S6_BH (GBN * ASTR)
#define S6_STG (3 * S6_AH + 3 * S6_BH)      // 23040 halves
#define S6_SMEM (2 * S6_STG * 2)            // 92160 bytes

__global__ void __launch_bounds__(256) gemm_split6_bf16(
    const __nv_bfloat16* __restrict__ Ah, const __nv_bfloat16* __restrict__ Am,
    const __nv_bfloat16* __restrict__ Al,
    const __nv_bfloat16* __restrict__ Wh, const __nv_bfloat16* __restrict__ Wm,
    const __nv_bfloat16* __restrict__ Wl,
    const float* __restrict__ bias, const float* __restrict__ bnp,
    float* __restrict__ Out, int M, int N, int K)
{
    extern __shared__ __align__(16) unsigned short sm[];
    uint32 smb = (uint32)__cvta_generic_to_shared(sm);

    int tid = threadIdx.x;
    int wid = tid >> 5, lane = tid & 31;
    int wm = wid & 3, wn = wid >> 2;
    int bn0 = blockIdx.x * GBN, bm0 = blockIdx.y * GBM;

    int ldrow = tid >> 2;
    int ldcol = (tid & 3) * 8;

    const __nv_bfloat16* Asel[3] = {Ah, Am, Al};
    const __nv_bfloat16* Wsel[3] = {Wh, Wm, Wl};

    float acc[2][4][4];
    #pragma unroll
    for (int mt = 0; mt < 2; mt++)
        #pragma unroll
        for (int nt = 0; nt < 4; nt++)
            #pragma unroll
            for (int q = 0; q < 4; q++) acc[mt][nt][q] = 0.0f;

    int a_row = (lane & 7) + ((lane >> 3) & 1) * 8;
    int a_ko  = ((lane >> 4) & 1) * 8;
    int b_row = (lane & 7) + ((lane >> 4) & 1) * 8;
    int b_ko  = ((lane >> 3) & 1) * 8;

    auto issue = [&](int st, int k0) {
        #pragma unroll
        for (int s = 0; s < 3; s++) {
            #pragma unroll
            for (int j = 0; j < 2; j++) {
                int row = ldrow + j * 64;
                uint32 dst = smb + (uint32)(st * S6_STG + s * S6_AH + row * ASTR + ldcol) * 2;
                CP16(dst, Asel[s] + (size_t)(bm0 + row) * K + k0 + ldcol);
            }
            uint32 dst = smb + (uint32)(st * S6_STG + 3 * S6_AH + s * S6_BH + ldrow * ASTR + ldcol) * 2;
            CP16(dst, Wsel[s] + (size_t)(bn0 + ldrow) * K + k0 + ldcol);
        }
    };

    int NCH = K / GBK;
    issue(0, 0);
    CP_COMMIT();

    for (int ch = 0; ch < NCH; ch++) {
        if (ch + 1 < NCH) issue((ch + 1) & 1, (ch + 1) * GBK);
        CP_COMMIT();
        CP_WAIT1();
        __syncthreads();

        int st = ch & 1;
        uint32 abase = smb + (uint32)(st * S6_STG) * 2;
        uint32 bbase = smb + (uint32)(st * S6_STG + 3 * S6_AH) * 2;

        #pragma unroll
        for (int ks = 0; ks < 2; ks++) {
            int kc = ks * 16;
            uint32 af[3][2][4];
            #pragma unroll
            for (int s = 0; s < 3; s++)
                #pragma unroll
                for (int mt = 0; mt < 2; mt++)
                    ldsm4(af[s][mt], abase + (uint32)(s * S6_AH + (wm * 32 + mt * 16 + a_row) * ASTR + kc + a_ko) * 2);
            #pragma unroll
            for (int t = 0; t < 3; t++) {
                #pragma unroll
                for (int g = 0; g < 2; g++) {
                    uint32 bf[4];
                    ldsm4(bf, bbase + (uint32)(t * S6_BH + (wn * 32 + g * 16 + b_row) * ASTR + kc + b_ko) * 2);
                    #pragma unroll
                    for (int s = 0; s < 3; s++) {
                        if (s + t <= 2) {
                            mma_bf16(acc[0][2 * g],     af[s][0], bf[0], bf[1]);
                            mma_bf16(acc[1][2 * g],     af[s][1], bf[0], bf[1]);
                            mma_bf16(acc[0][2 * g + 1], af[s][0], bf[2], bf[3]);
                            mma_bf16(acc[1][2 * g + 1], af[s][1], bf[2], bf[3]);
                        }
                    }
                }
            }
        }
        __syncthreads();
    }

    int r4 = lane >> 2, c2 = (lane & 3) * 2;
    #pragma unroll
    for (int nt = 0; nt < 4; nt++) {
        int n0 = bn0 + wn * 32 + nt * 8 + c2;
        float g0 = bnp[n0],     be0 = bnp[N + n0],     mm0 = bnp[2*N + n0],     vv0 = bnp[3*N + n0];
        float g1 = bnp[n0 + 1], be1 = bnp[N + n0 + 1], mm1 = bnp[2*N + n0 + 1], vv1 = bnp[3*N + n0 + 1];
        float sc0 = g0 / sqrtf(vv0 + EPSF), sh0 = be0 - mm0 * sc0;
        float sc1 = g1 / sqrtf(vv1 + EPSF), sh1 = be1 - mm1 * sc1;
        float bs0 = bias[n0], bs1 = bias[n0 + 1];
        #pragma unroll
        for (int mt = 0; mt < 2; mt++) {
            int m0 = bm0 + wm * 32 + mt * 16 + r4;
            float2 o0, o1;
            o0.x = (acc[mt][nt][0] + bs0) * sc0 + sh0;
            o0.y = (acc[mt][nt][1] + bs1) * sc1 + sh1;
            o1.x = (acc[mt][nt][2] + bs0) * sc0 + sh0;
            o1.y = (acc[mt][nt][3] + bs1) * sc1 + sh1;
            *(float2*)&Out[(size_t)m0 * N + n0] = o0;
            *(float2*)&Out[(size_t)(m0 + 8) * N + n0] = o1;
        }
    }
}

// ---------------- LIF scan ----------------
template<typename OutT>
__global__ void __launch_bounds__(256) lif_kernel(
    const float* __restrict__ X, int ldx,
    const float* __restrict__ Mul, int ldm,
    const float* __restrict__ bnp,
    OutT* __restrict__ S)
{
    int j = blockIdx.x * blockDim.x + threadIdx.x;
    if (j >= B_DIM * C_DIM) return;
    int b = j / C_DIM, c = j % C_DIM;

    float sc = 1.0f, sh = 0.0f;
    if (bnp) {
        float g = bnp[c], be = bnp[C_DIM + c], mm = bnp[2 * C_DIM + c], vv = bnp[3 * C_DIM + c];
        sc = g / sqrtf(vv + EPSF);
        sh = be - mm * sc;
    }

    const float* xp = X + (size_t)b * ldx + c;
    const float* mp = Mul ? (Mul + (size_t)b * ldm + c) : nullptr;
    OutT* sp = S + (size_t)j;
    size_t stx = (size_t)B_DIM * ldx;
    size_t stm = (size_t)B_DIM * ldm;
    size_t sts = (size_t)B_DIM * C_DIM;

    float vm = 0.0f;
    #pragma unroll 4
    for (int t = 0; t < T_DIM; t++) {
        float xv = xp[(size_t)t * stx];
        if (mp) xv *= mp[(size_t)t * stm];
        xv = xv * sc + sh;
        vm = vm * 0.5f + xv;
        float s = (vm >= 1.0f) ? 1.0f : 0.0f;
        vm = (s > 0.0f) ? 0.0f : vm;
        sp[(size_t)t * sts] = (OutT)s;
    }
}

// ---------------- depthwise conv over time ----------------
#define DW_PAD 15
__global__ void __launch_bounds__(256) dw_kernel(
    const float* __restrict__ S1, const float* __restrict__ w,
    const float* __restrict__ bvec, float* __restrict__ Dout)
{
    __shared__ float sx[T_DIM + 2 * DW_PAD][64];
    int b  = blockIdx.x;
    int c0 = blockIdx.y * 64;
    int tid = threadIdx.x;

    for (int i = tid; i < 2 * DW_PAD * 64; i += 256) {
        int r = i >> 6, ci = i & 63;
        if (r < DW_PAD) sx[r][ci] = 0.0f;
        else            sx[T_DIM + DW_PAD + (r - DW_PAD)][ci] = 0.0f;
    }
    for (int i = tid; i < T_DIM * 64; i += 256) {
        int t = i >> 6, ci = i & 63;
        sx[t + DW_PAD][ci] = S1[((size_t)t * B_DIM + b) * C_DIM + c0 + ci];
    }
    __syncthreads();

    int ci = tid & 63;
    int tg = tid >> 6;
    int c  = c0 + ci;
    int t0 = tg * 32;

    float wr[K_DW];
    #pragma unroll
    for (int k = 0; k < K_DW; k++) wr[k] = w[c * K_DW + k];
    float bb = bvec[c];

    float acc[32];
    #pragma unroll
    for (int i = 0; i < 32; i++) acc[i] = bb;

    #pragma unroll
    for (int dt = -DW_PAD; dt <= 31 + DW_PAD; dt++) {
        float sv = sx[t0 + dt + DW_PAD][ci];
        #pragma unroll
        for (int i = 0; i < 32; i++) {
            int k = dt - i + DW_PAD;
            if (k >= 0 && k < K_DW) acc[i] += sv * wr[k];
        }
    }

    #pragma unroll
    for (int i = 0; i < 32; i++) {
        int t = t0 + i;
        Dout[((size_t)t * B_DIM + b) * C_DIM + c] = acc[i];
    }
}

// ---------------- launch ----------------
extern "C" void kernel_launch(void* const* d_in, const int* in_sizes, int n_in,
                              void* d_out, int out_size)
{
    const float* x        = (const float*)d_in[0];
    const float* ln_g     = (const float*)d_in[1];
    const float* ln_b     = (const float*)d_in[2];
    const float* pw1_w    = (const float*)d_in[3];
    const float* pw1_b    = (const float*)d_in[4];
    const float* bn1_p    = (const float*)d_in[5];
    const float* dw_w     = (const float*)d_in[6];
    const float* dw_b     = (const float*)d_in[7];
    const float* bn2_p    = (const float*)d_in[8];
    const float* pw2_w    = (const float*)d_in[9];
    const float* pw2_b    = (const float*)d_in[10];
    const float* bn3_p    = (const float*)d_in[11];
    const float* gsu_w    = (const float*)d_in[12];
    const float* gsu_b    = (const float*)d_in[13];
    const float* gsu_bn_p = (const float*)d_in[14];

    float *Y1, *S1, *D, *Y2, *Y3, *Sg2;
    __nv_bfloat16 *S2b, *Sgb, *Hh, *Hm, *Hl;
    __nv_bfloat16 *W1hi, *W1mi, *W1lo, *W2hi, *W2mi, *W2lo, *Wghi, *Wgmi, *Wglo;
    cudaGetSymbolAddress((void**)&Y1,   g_Y1);
    cudaGetSymbolAddress((void**)&S1,   g_S1);
    cudaGetSymbolAddress((void**)&D,    g_D);
    cudaGetSymbolAddress((void**)&Y2,   g_Y2);
    cudaGetSymbolAddress((void**)&Y3,   g_Y3);
    cudaGetSymbolAddress((void**)&Sg2,  g_Sg2);
    cudaGetSymbolAddress((void**)&S2b,  g_S2b);
    cudaGetSymbolAddress((void**)&Sgb,  g_Sgb);
    cudaGetSymbolAddress((void**)&Hh,   g_Hh);
    cudaGetSymbolAddress((void**)&Hm,   g_Hm);
    cudaGetSymbolAddress((void**)&Hl,   g_Hl);
    cudaGetSymbolAddress((void**)&W1hi, g_W1hi);
    cudaGetSymbolAddress((void**)&W1mi, g_W1mi);
    cudaGetSymbolAddress((void**)&W1lo, g_W1lo);
    cudaGetSymbolAddress((void**)&W2hi, g_W2hi);
    cudaGetSymbolAddress((void**)&W2mi, g_W2mi);
    cudaGetSymbolAddress((void**)&W2lo, g_W2lo);
    cudaGetSymbolAddress((void**)&Wghi, g_Wghi);
    cudaGetSymbolAddress((void**)&Wgmi, g_Wgmi);
    cudaGetSymbolAddress((void**)&Wglo, g_Wglo);

    // idempotent, called every invocation (no static guards per harness rules)
    cudaFuncSetAttribute(gemm_spike_bf16,
        cudaFuncAttributeMaxDynamicSharedMemorySize, SPIKE_SMEM);
    cudaFuncSetAttribute(gemm_split6_bf16,
        cudaFuncAttributeMaxDynamicSharedMemorySize, S6_SMEM);

    const int lif_blocks = (B_DIM * C_DIM + 255) / 256;   // 192

    // 0) weight splits
    split_w_kernel<<<(C_DIM * C_DIM + 255) / 256, 256>>>(pw1_w, W1hi, W1mi, W1lo, C_DIM * C_DIM);
    split_w_kernel<<<(2 * C_DIM * C_DIM + 255) / 256, 256>>>(pw2_w, W2hi, W2mi, W2lo, 2 * C_DIM * C_DIM);
    split_w_kernel<<<(C_DIM * C_DIM + 255) / 256, 256>>>(gsu_w, Wghi, Wgmi, Wglo, C_DIM * C_DIM);

    // 1) LayerNorm -> H splits (bf16 x3)
    ln_kernel<<<M_DIM, 256>>>(x, ln_g, ln_b, Hh, Hm, Hl);

    // 2) pw1 + bias + bn1 (tensor, 6-term split)
    gemm_split6_bf16<<<dim3(C_DIM / GBN, M_DIM / GBM), 256, S6_SMEM>>>(
        Hh, Hm, Hl, W1hi, W1mi, W1lo, pw1_b, bn1_p, Y1, M_DIM, C_DIM, C_DIM);

    // 3) LIF -> S1
    lif_kernel<float><<<lif_blocks, 256>>>(Y1, C_DIM, nullptr, 0, nullptr, S1);

    // 4) depthwise
    dw_kernel<<<dim3(B_DIM, C_DIM / 64), 256>>>(S1, dw_w, dw_b, D);

    // 5) BN2 + LIF -> S2 (bf16)
    lif_kernel<__nv_bfloat16><<<lif_blocks, 256>>>(D, C_DIM, nullptr, 0, bn2_p, S2b);

    // 6) pw2 + bias + bn3 (tensor)
    gemm_spike_bf16<<<dim3(2 * C_DIM / GBN, M_DIM / GBM), 256, SPIKE_SMEM>>>(
        S2b, W2hi, W2mi, W2lo, pw2_b, bn3_p, Y2, M_DIM, 2 * C_DIM, C_DIM);

    // 7) LIF(gate) -> Sg (bf16)
    lif_kernel<__nv_bfloat16><<<lif_blocks, 256>>>(Y2 + C_DIM, 2 * C_DIM, nullptr, 0, nullptr, Sgb);

    // 8) gsu GEMM (tensor)
    gemm_spike_bf16<<<dim3(C_DIM / GBN, M_DIM / GBM), 256, SPIKE_SMEM>>>(
        Sgb, Wghi, Wgmi, Wglo, gsu_b, gsu_bn_p, Y3, M_DIM, C_DIM, C_DIM);

    // 9) LIF -> Sg2
    lif_kernel<float><<<lif_blocks, 256>>>(Y3, C_DIM, nullptr, 0, nullptr, Sg2);

    // 10) final LIF on out*Sg2 -> d_out
    lif_kernel<float><<<lif_blocks, 256>>>(Y2, 2 * C_DIM, Sg2, C_DIM, nullptr, (float*)d_out);
}